// round 10
// baseline (speedup 1.0000x reference)
#include <cuda_runtime.h>
#include <cuda_bf16.h>
#include <math_constants.h>
#include <cstdint>

#define BB 16
#define HH 16
#define SDIM 512
#define DDIM 64
#define QT 64
#define THREADS 512
#define KSTRB 144

#define L_ATT 0.33f
#define L_DIST 0.33f
#define L_ADJ (1.0f - 0.33f - 0.33f)

// ---- smem map (bytes) ----
#define OFF_QS   0
#define OFF_K    18432
#define OFF_V    55296
#define OFF_RED  202752
#define RSTR     68
#define OFF_RM   220160
#define OFF_RS   221184
#define OFF_MASK 222208
#define SMEM_BYTES 224256
// reduction partial regions (dead Q/K smem + sRed), 64*68*4 = 17408 B each
#define REDB0 0
#define REDB1 18432
#define REDB2 36864
#define REDB3 OFF_RED

__device__ float g_C[(size_t)BB * SDIM * SDIM];

__global__ __launch_bounds__(256) void precompute_C_kernel(
    const float* __restrict__ adj, const float* __restrict__ dist,
    const float* __restrict__ mask)
{
    int row = blockIdx.x;
    int b = row >> 9;
    const float* arow = adj  + (size_t)row * SDIM;
    const float* drow = dist + (size_t)row * SDIM;
    const float* mrow = mask + (size_t)b * SDIM;
    float* crow = g_C + (size_t)row * SDIM;
    int tid = threadIdx.x, w = tid >> 5, l = tid & 31;

    float a0 = arow[tid], a1 = arow[tid + 256];
    float d0 = drow[tid], d1 = drow[tid + 256];
    float m0 = mrow[tid], m1 = mrow[tid + 256];
    float x0 = (m0 == 0.0f) ? -CUDART_INF_F : -d0;
    float x1 = (m1 == 0.0f) ? -CUDART_INF_F : -d1;

    float asum = a0 + a1, xmax = fmaxf(x0, x1);
    #pragma unroll
    for (int o = 16; o > 0; o >>= 1) {
        asum += __shfl_xor_sync(0xffffffffu, asum, o);
        xmax = fmaxf(xmax, __shfl_xor_sync(0xffffffffu, xmax, o));
    }
    __shared__ float rs[8], rm[8], re[8];
    if (l == 0) { rs[w] = asum; rm[w] = xmax; }
    __syncthreads();
    float ts = 0.0f, tm = -CUDART_INF_F;
    #pragma unroll
    for (int i = 0; i < 8; i++) { ts += rs[i]; tm = fmaxf(tm, rm[i]); }

    float e0 = __expf(x0 - tm), e1 = __expf(x1 - tm), es = e0 + e1;
    #pragma unroll
    for (int o = 16; o > 0; o >>= 1) es += __shfl_xor_sync(0xffffffffu, es, o);
    if (l == 0) re[w] = es;
    __syncthreads();
    float te = 0.0f;
    #pragma unroll
    for (int i = 0; i < 8; i++) te += re[i];

    float inv_a = 1.0f / (ts + 1e-6f), inv_e = 1.0f / te;
    crow[tid]       = L_DIST * e0 * inv_e + L_ADJ * a0 * inv_a;
    crow[tid + 256] = L_DIST * e1 * inv_e + L_ADJ * a1 * inv_a;
}

__device__ __forceinline__ void mma_bf16(float* c, const uint32_t* a, const uint32_t* b) {
    asm volatile("mma.sync.aligned.m16n8k16.row.col.f32.bf16.bf16.f32 "
        "{%0,%1,%2,%3}, {%4,%5,%6,%7}, {%8,%9}, {%0,%1,%2,%3};"
        : "+f"(c[0]), "+f"(c[1]), "+f"(c[2]), "+f"(c[3])
        : "r"(a[0]), "r"(a[1]), "r"(a[2]), "r"(a[3]), "r"(b[0]), "r"(b[1]));
}
__device__ __forceinline__ void ldm_x4(uint32_t* r, uint32_t a) {
    asm volatile("ldmatrix.sync.aligned.m8n8.x4.shared.b16 {%0,%1,%2,%3}, [%4];"
        : "=r"(r[0]), "=r"(r[1]), "=r"(r[2]), "=r"(r[3]) : "r"(a));
}
__device__ __forceinline__ void ldm_x4t(uint32_t* r, uint32_t a) {
    asm volatile("ldmatrix.sync.aligned.m8n8.x4.trans.shared.b16 {%0,%1,%2,%3}, [%4];"
        : "=r"(r[0]), "=r"(r[1]), "=r"(r[2]), "=r"(r[3]) : "r"(a));
}
__device__ __forceinline__ uint32_t smem_u32(const void* p) {
    uint32_t a;
    asm("{ .reg .u64 t; cvta.to.shared.u64 t, %1; cvt.u32.u64 %0, t; }" : "=r"(a) : "l"(p));
    return a;
}
__device__ __forceinline__ uint32_t packbf(float lo, float hi) {
    uint32_t r;
    asm("cvt.rn.bf16x2.f32 %0, %1, %2;" : "=r"(r) : "f"(hi), "f"(lo));
    return r;
}
__device__ __forceinline__ float bfround(float x) {
    return __bfloat162float(__float2bfloat16_rn(x));
}

__global__ __launch_bounds__(512) void attn_mma_kernel(
    const float* __restrict__ Q, const float* __restrict__ K,
    const float* __restrict__ V, const float* __restrict__ mask,
    float* __restrict__ Og, float* __restrict__ Pg)
{
    extern __shared__ char smem[];
    uint32_t sb = smem_u32(smem);
    float* sMask = (float*)(smem + OFF_MASK);

    int tid = threadIdx.x;
    int wid = tid >> 5, l = tid & 31;
    int lr = l >> 2, lc = l & 3;
    int lr8 = l & 7, lg = (l >> 3) & 1, kg4 = l >> 4;
    int wm = wid >> 2, wn = wid & 3;

    int qt = blockIdx.x, h = blockIdx.y, b = blockIdx.z;
    int q0 = qt * QT;
    size_t bh_ = (size_t)b * HH + h;
    const float* Qp = Q + (bh_ * SDIM + q0) * DDIM;
    const float* Kp = K + bh_ * SDIM * DDIM;
    const float* Vp = V + bh_ * SDIM * DDIM;
    const float* Mp = mask + (size_t)b * SDIM;
    const float* Cp = g_C + ((size_t)b * SDIM + q0) * SDIM;
    float* Op = Og + (bh_ * SDIM + q0) * DDIM;
    float* Pp = Pg + (bh_ * SDIM + q0) * SDIM;

    sMask[tid] = Mp[tid];

    // ---- Q (x 1/8) -> hi/lo bf16 smem ----
    {
        const float4* Q4 = (const float4*)Qp;
        #pragma unroll
        for (int t = 0; t < 2; ++t) {
            int idx = tid + 512 * t;
            float4 f = Q4[idx];
            int r = idx >> 4, c = (idx & 15) << 2;
            float v0 = f.x * 0.125f, v1 = f.y * 0.125f, v2 = f.z * 0.125f, v3 = f.w * 0.125f;
            char* dst = smem + OFF_QS + r * KSTRB + 2 * c;
            *(uint2*)dst = make_uint2(packbf(v0, v1), packbf(v2, v3));
            *(uint2*)(dst + 9216) = make_uint2(
                packbf(v0 - bfround(v0), v1 - bfround(v1)),
                packbf(v2 - bfround(v2), v3 - bfround(v3)));
        }
    }
    // ---- K tile 0 -> buf0; prefetch tile 1 ----
    {
        const float4* K4 = (const float4*)Kp;
        #pragma unroll
        for (int t = 0; t < 2; ++t) {
            int idx = tid + 512 * t;
            float4 f = K4[idx];
            int r = idx >> 4, c = (idx & 15) << 2;
            char* dst = smem + OFF_K + r * KSTRB + 2 * c;
            *(uint2*)dst = make_uint2(packbf(f.x, f.y), packbf(f.z, f.w));
            *(uint2*)(dst + 9216) = make_uint2(
                packbf(f.x - bfround(f.x), f.y - bfround(f.y)),
                packbf(f.z - bfround(f.z), f.w - bfround(f.w)));
        }
    }
    float4 pf[2];
    {
        const float4* K4 = (const float4*)(Kp + 4096);
        pf[0] = K4[tid]; pf[1] = K4[tid + 512];
    }
    __syncthreads();

    // ---- resident Q fragments ----
    uint32_t qah[4][4], qal[4][4];
    {
        uint32_t ra = sb + OFF_QS + (16 * wm + lr8 + 8 * lg) * KSTRB + 16 * kg4;
        #pragma unroll
        for (int ks = 0; ks < 4; ++ks) {
            ldm_x4(qah[ks], ra + ks * 32);
            ldm_x4(qal[ks], ra + 9216 + ks * 32);
        }
    }

    // ---- Phase 1: scores (regs) + V staging interleaved ----
    const float4* V4 = (const float4*)Vp;
    float sc[8][2][4];
    #pragma unroll
    for (int kt = 0; kt < 8; ++kt) {
        // V chunk LDGs for this iteration (latency covered by mma block)
        float4 vf0 = V4[tid + 512 * (2 * kt)];
        float4 vf1 = V4[tid + 512 * (2 * kt + 1)];

        #pragma unroll
        for (int nf = 0; nf < 2; ++nf)
            #pragma unroll
            for (int e = 0; e < 4; ++e) sc[kt][nf][e] = 0.0f;

        uint32_t rbase = sb + OFF_K + (kt & 1) * 18432
                         + (16 * wn + lr8 + 8 * kg4) * KSTRB + 16 * lg;
        uint32_t bh[2][4];
        ldm_x4(bh[0], rbase);
        #pragma unroll
        for (int ks = 0; ks < 4; ++ks) {
            int cc = ks & 1;
            if (ks < 3) ldm_x4(bh[cc ^ 1], rbase + 32 * (ks + 1));
            uint32_t bl[4];
            ldm_x4(bl, rbase + 9216 + 32 * ks);
            #pragma unroll
            for (int nf = 0; nf < 2; ++nf) {
                mma_bf16(sc[kt][nf], qah[ks], bh[cc] + 2 * nf);
                mma_bf16(sc[kt][nf], qal[ks], bh[cc] + 2 * nf);
                mma_bf16(sc[kt][nf], qah[ks], bl + 2 * nf);
            }
        }
        if (kt < 7) {
            #pragma unroll
            for (int t = 0; t < 2; ++t) {
                int idx = tid + 512 * t;
                float4 f = pf[t];
                int r = idx >> 4, c = (idx & 15) << 2;
                char* dst = smem + OFF_K + ((kt + 1) & 1) * 18432 + r * KSTRB + 2 * c;
                *(uint2*)dst = make_uint2(packbf(f.x, f.y), packbf(f.z, f.w));
                *(uint2*)(dst + 9216) = make_uint2(
                    packbf(f.x - bfround(f.x), f.y - bfround(f.y)),
                    packbf(f.z - bfround(f.z), f.w - bfround(f.w)));
            }
            __syncthreads();
            if (kt < 6) {
                const float4* K4 = (const float4*)(Kp + (size_t)(kt + 2) * 4096);
                pf[0] = K4[tid]; pf[1] = K4[tid + 512];
            }
        }
        // V chunk STS (region disjoint from K buffers; consumed after RS barrier)
        {
            int idx = tid + 512 * (2 * kt);
            int r = idx >> 4, c = (idx & 15) << 2;
            char* dst = smem + OFF_V + r * KSTRB + 2 * c;
            *(uint2*)dst = make_uint2(packbf(vf0.x, vf0.y), packbf(vf0.z, vf0.w));
            *(uint2*)(dst + 73728) = make_uint2(
                packbf(vf0.x - bfround(vf0.x), vf0.y - bfround(vf0.y)),
                packbf(vf0.z - bfround(vf0.z), vf0.w - bfround(vf0.w)));
            idx += 512;
            r = idx >> 4; c = (idx & 15) << 2;
            dst = smem + OFF_V + r * KSTRB + 2 * c;
            *(uint2*)dst = make_uint2(packbf(vf1.x, vf1.y), packbf(vf1.z, vf1.w));
            *(uint2*)(dst + 73728) = make_uint2(
                packbf(vf1.x - bfround(vf1.x), vf1.y - bfround(vf1.y)),
                packbf(vf1.z - bfround(vf1.z), vf1.w - bfround(vf1.w)));
        }
    }

    // ---- softmax reductions (scores stay in regs) ----
    int r0 = 16 * wm + lr, r1 = r0 + 8;
    {
        float2 mk;
        #pragma unroll
        for (int j = 0; j < 8; ++j)
            #pragma unroll
            for (int nf = 0; nf < 2; ++nf) {
                mk = *(float2*)(smem + OFF_MASK + 4 * (64 * j + 16 * wn + 8 * nf + 2 * lc));
                if (mk.x == 0.0f) { sc[j][nf][0] = -1e12f; sc[j][nf][2] = -1e12f; }
                if (mk.y == 0.0f) { sc[j][nf][1] = -1e12f; sc[j][nf][3] = -1e12f; }
            }
    }
    float mx0 = -CUDART_INF_F, mx1 = -CUDART_INF_F;
    #pragma unroll
    for (int j = 0; j < 8; ++j)
        #pragma unroll
        for (int nf = 0; nf < 2; ++nf) {
            mx0 = fmaxf(mx0, fmaxf(sc[j][nf][0], sc[j][nf][1]));
            mx1 = fmaxf(mx1, fmaxf(sc[j][nf][2], sc[j][nf][3]));
        }
    #pragma unroll
    for (int o = 1; o < 4; o <<= 1) {
        mx0 = fmaxf(mx0, __shfl_xor_sync(0xffffffffu, mx0, o));
        mx1 = fmaxf(mx1, __shfl_xor_sync(0xffffffffu, mx1, o));
    }
    if (lc == 0) {
        ((float*)(smem + OFF_RM))[r0 * 4 + wn] = mx0;
        ((float*)(smem + OFF_RM))[r1 * 4 + wn] = mx1;
    }
    __syncthreads();
    {
        float4 m0 = *(float4*)(smem + OFF_RM + r0 * 16);
        float4 m1 = *(float4*)(smem + OFF_RM + r1 * 16);
        mx0 = fmaxf(fmaxf(m0.x, m0.y), fmaxf(m0.z, m0.w));
        mx1 = fmaxf(fmaxf(m1.x, m1.y), fmaxf(m1.z, m1.w));
    }
    float s0 = 0.0f, s1 = 0.0f;
    #pragma unroll
    for (int j = 0; j < 8; ++j)
        #pragma unroll
        for (int nf = 0; nf < 2; ++nf) {
            sc[j][nf][0] = __expf(sc[j][nf][0] - mx0);
            sc[j][nf][1] = __expf(sc[j][nf][1] - mx0);
            sc[j][nf][2] = __expf(sc[j][nf][2] - mx1);
            sc[j][nf][3] = __expf(sc[j][nf][3] - mx1);
            s0 += sc[j][nf][0] + sc[j][nf][1];
            s1 += sc[j][nf][2] + sc[j][nf][3];
        }
    #pragma unroll
    for (int o = 1; o < 4; o <<= 1) {
        s0 += __shfl_xor_sync(0xffffffffu, s0, o);
        s1 += __shfl_xor_sync(0xffffffffu, s1, o);
    }
    if (lc == 0) {
        ((float*)(smem + OFF_RS))[r0 * 4 + wn] = s0;
        ((float*)(smem + OFF_RS))[r1 * 4 + wn] = s1;
    }

    // prefetch first C chunk while waiting on the sum barrier
    int colb = 16 * wn + 2 * lc;
    float2 cb[2][2][2];
    #pragma unroll
    for (int nf = 0; nf < 2; ++nf) {
        cb[0][0][nf] = __ldg((const float2*)(Cp + (size_t)r0 * SDIM + colb + 8 * nf));
        cb[0][1][nf] = __ldg((const float2*)(Cp + (size_t)r1 * SDIM + colb + 8 * nf));
    }
    __syncthreads();
    float inv0, inv1;
    {
        float4 t0 = *(float4*)(smem + OFF_RS + r0 * 16);
        float4 t1 = *(float4*)(smem + OFF_RS + r1 * 16);
        inv0 = 1.0f / (t0.x + t0.y + t0.z + t0.w);
        inv1 = 1.0f / (t1.x + t1.y + t1.z + t1.w);
    }

    // ---- fused phase 2+3 per 64-key chunk j, C prefetched, V frags pipelined ----
    float accO[8][4];
    #pragma unroll
    for (int nj = 0; nj < 8; ++nj)
        #pragma unroll
        for (int e = 0; e < 4; ++e) accO[nj][e] = 0.0f;

    #pragma unroll
    for (int j = 0; j < 8; ++j) {
        int cur = j & 1, nxt = cur ^ 1;
        if (j < 7) {
            int coln = 64 * (j + 1) + colb;
            #pragma unroll
            for (int nf = 0; nf < 2; ++nf) {
                cb[nxt][0][nf] = __ldg((const float2*)(Cp + (size_t)r0 * SDIM + coln + 8 * nf));
                cb[nxt][1][nf] = __ldg((const float2*)(Cp + (size_t)r1 * SDIM + coln + 8 * nf));
            }
        }
        uint32_t wah[4], wal[4];
        #pragma unroll
        for (int nf = 0; nf < 2; ++nf) {
            int col = 64 * j + colb + 8 * nf;
            float p00 = sc[j][nf][0] * inv0, p01 = sc[j][nf][1] * inv0;
            float p10 = sc[j][nf][2] * inv1, p11 = sc[j][nf][3] * inv1;
            __stcs((float2*)(Pp + (size_t)r0 * SDIM + col), make_float2(p00, p01));
            __stcs((float2*)(Pp + (size_t)r1 * SDIM + col), make_float2(p10, p11));
            float w00 = fmaf(L_ATT, p00, cb[cur][0][nf].x);
            float w01 = fmaf(L_ATT, p01, cb[cur][0][nf].y);
            float w10 = fmaf(L_ATT, p10, cb[cur][1][nf].x);
            float w11 = fmaf(L_ATT, p11, cb[cur][1][nf].y);
            wah[2 * nf]     = packbf(w00, w01);
            wah[2 * nf + 1] = packbf(w10, w11);
            wal[2 * nf]     = packbf(w00 - bfround(w00), w01 - bfround(w01));
            wal[2 * nf + 1] = packbf(w10 - bfround(w10), w11 - bfround(w11));
        }

        uint32_t vrow = sb + OFF_V + (64 * j + 16 * wn + lr8 + 8 * lg) * KSTRB + 73728 * kg4;
        uint32_t vb[2][4];
        ldm_x4t(vb[0], vrow);
        #pragma unroll
        for (int nj = 0; nj < 8; ++nj) {
            int vc = nj & 1;
            if (nj < 7) ldm_x4t(vb[vc ^ 1], vrow + 16 * (nj + 1));
            mma_bf16(accO[nj], wah, vb[vc]);
            mma_bf16(accO[nj], wal, vb[vc]);
            mma_bf16(accO[nj], wah, vb[vc] + 2);
        }
    }

    // ---- parallel reduction: 4 disjoint regions, one barrier ----
    __syncthreads();   // all reads of Q/K smem regions complete (phase 1 done long ago)
    {
        static const int REDB[4] = {REDB0, REDB1, REDB2, REDB3};
        char* reg_ = smem + REDB[wn];
        #pragma unroll
        for (int nj = 0; nj < 8; ++nj) {
            int col = 8 * nj + 2 * lc;
            *(float2*)(reg_ + (r0 * RSTR + col) * 4) = make_float2(accO[nj][0], accO[nj][1]);
            *(float2*)(reg_ + (r1 * RSTR + col) * 4) = make_float2(accO[nj][2], accO[nj][3]);
        }
    }
    __syncthreads();

    #pragma unroll
    for (int t = 0; t < 2; ++t) {
        int idx = tid + 512 * t;
        int row = idx >> 4, c0 = (idx & 15) << 2;
        float4 a0 = *(float4*)(smem + REDB0 + (row * RSTR + c0) * 4);
        float4 a1 = *(float4*)(smem + REDB1 + (row * RSTR + c0) * 4);
        float4 a2 = *(float4*)(smem + REDB2 + (row * RSTR + c0) * 4);
        float4 a3 = *(float4*)(smem + REDB3 + (row * RSTR + c0) * 4);
        float4 o;
        o.x = (a0.x + a1.x) + (a2.x + a3.x);
        o.y = (a0.y + a1.y) + (a2.y + a3.y);
        o.z = (a0.z + a1.z) + (a2.z + a3.z);
        o.w = (a0.w + a1.w) + (a2.w + a3.w);
        *(float4*)(Op + row * DDIM + c0) = o;
    }
}

extern "C" void kernel_launch(void* const* d_in, const int* in_sizes, int n_in,
                              void* d_out, int out_size)
{
    const float* Q    = (const float*)d_in[0];
    const float* K    = (const float*)d_in[1];
    const float* V    = (const float*)d_in[2];
    const float* mask = (const float*)d_in[3];
    const float* adj  = (const float*)d_in[4];
    const float* dist = (const float*)d_in[5];

    float* outp  = (float*)d_out;
    float* pattn = outp + (size_t)BB * HH * SDIM * DDIM;

    precompute_C_kernel<<<BB * SDIM, 256>>>(adj, dist, mask);

    cudaFuncSetAttribute(attn_mma_kernel,
                         cudaFuncAttributeMaxDynamicSharedMemorySize, SMEM_BYTES);
    dim3 grid(SDIM / QT, HH, BB);
    attn_mma_kernel<<<grid, THREADS, SMEM_BYTES>>>(Q, K, V, mask, outp, pattn);
}

// round 11
// speedup vs baseline: 1.0018x; 1.0018x over previous
#include <cuda_runtime.h>
#include <cuda_bf16.h>
#include <math_constants.h>
#include <cstdint>

#define BB 16
#define HH 16
#define SDIM 512
#define DDIM 64
#define QT 64
#define THREADS 512
#define KSTRB 144

#define L_ATT 0.33f
#define L_DIST 0.33f
#define L_ADJ (1.0f - 0.33f - 0.33f)

// ---- smem map (bytes) ----
#define OFF_QS   0
#define OFF_K    18432
#define OFF_V    55296
#define OFF_RED  202752
#define RSTR     68
#define OFF_RM   220160
#define OFF_RS   221184
#define OFF_MASK 222208
#define SMEM_BYTES 224256
// reduction partial regions (dead Q/K smem + sRed), 64*68*4 = 17408 B each
#define REDB0 0
#define REDB1 18432
#define REDB2 36864
#define REDB3 OFF_RED

__device__ float g_C[(size_t)BB * SDIM * SDIM];

__global__ __launch_bounds__(256) void precompute_C_kernel(
    const float* __restrict__ adj, const float* __restrict__ dist,
    const float* __restrict__ mask)
{
    int row = blockIdx.x;
    int b = row >> 9;
    const float* arow = adj  + (size_t)row * SDIM;
    const float* drow = dist + (size_t)row * SDIM;
    const float* mrow = mask + (size_t)b * SDIM;
    float* crow = g_C + (size_t)row * SDIM;
    int tid = threadIdx.x, w = tid >> 5, l = tid & 31;

    float a0 = arow[tid], a1 = arow[tid + 256];
    float d0 = drow[tid], d1 = drow[tid + 256];
    float m0 = mrow[tid], m1 = mrow[tid + 256];
    float x0 = (m0 == 0.0f) ? -CUDART_INF_F : -d0;
    float x1 = (m1 == 0.0f) ? -CUDART_INF_F : -d1;

    float asum = a0 + a1, xmax = fmaxf(x0, x1);
    #pragma unroll
    for (int o = 16; o > 0; o >>= 1) {
        asum += __shfl_xor_sync(0xffffffffu, asum, o);
        xmax = fmaxf(xmax, __shfl_xor_sync(0xffffffffu, xmax, o));
    }
    __shared__ float rs[8], rm[8], re[8];
    if (l == 0) { rs[w] = asum; rm[w] = xmax; }
    __syncthreads();
    float ts = 0.0f, tm = -CUDART_INF_F;
    #pragma unroll
    for (int i = 0; i < 8; i++) { ts += rs[i]; tm = fmaxf(tm, rm[i]); }

    float e0 = __expf(x0 - tm), e1 = __expf(x1 - tm), es = e0 + e1;
    #pragma unroll
    for (int o = 16; o > 0; o >>= 1) es += __shfl_xor_sync(0xffffffffu, es, o);
    if (l == 0) re[w] = es;
    __syncthreads();
    float te = 0.0f;
    #pragma unroll
    for (int i = 0; i < 8; i++) te += re[i];

    float inv_a = 1.0f / (ts + 1e-6f), inv_e = 1.0f / te;
    crow[tid]       = L_DIST * e0 * inv_e + L_ADJ * a0 * inv_a;
    crow[tid + 256] = L_DIST * e1 * inv_e + L_ADJ * a1 * inv_a;
}

__device__ __forceinline__ void mma_bf16(float* c, const uint32_t* a, const uint32_t* b) {
    asm volatile("mma.sync.aligned.m16n8k16.row.col.f32.bf16.bf16.f32 "
        "{%0,%1,%2,%3}, {%4,%5,%6,%7}, {%8,%9}, {%0,%1,%2,%3};"
        : "+f"(c[0]), "+f"(c[1]), "+f"(c[2]), "+f"(c[3])
        : "r"(a[0]), "r"(a[1]), "r"(a[2]), "r"(a[3]), "r"(b[0]), "r"(b[1]));
}
__device__ __forceinline__ void ldm_x4(uint32_t* r, uint32_t a) {
    asm volatile("ldmatrix.sync.aligned.m8n8.x4.shared.b16 {%0,%1,%2,%3}, [%4];"
        : "=r"(r[0]), "=r"(r[1]), "=r"(r[2]), "=r"(r[3]) : "r"(a));
}
__device__ __forceinline__ void ldm_x4t(uint32_t* r, uint32_t a) {
    asm volatile("ldmatrix.sync.aligned.m8n8.x4.trans.shared.b16 {%0,%1,%2,%3}, [%4];"
        : "=r"(r[0]), "=r"(r[1]), "=r"(r[2]), "=r"(r[3]) : "r"(a));
}
__device__ __forceinline__ uint32_t smem_u32(const void* p) {
    uint32_t a;
    asm("{ .reg .u64 t; cvta.to.shared.u64 t, %1; cvt.u32.u64 %0, t; }" : "=r"(a) : "l"(p));
    return a;
}
__device__ __forceinline__ uint32_t packbf(float lo, float hi) {
    uint32_t r;
    asm("cvt.rn.bf16x2.f32 %0, %1, %2;" : "=r"(r) : "f"(hi), "f"(lo));
    return r;
}
__device__ __forceinline__ float bfround(float x) {
    return __bfloat162float(__float2bfloat16_rn(x));
}

__global__ __launch_bounds__(512) void attn_mma_kernel(
    const float* __restrict__ Q, const float* __restrict__ K,
    const float* __restrict__ V, const float* __restrict__ mask,
    float* __restrict__ Og, float* __restrict__ Pg)
{
    extern __shared__ char smem[];
    uint32_t sb = smem_u32(smem);
    float* sMask = (float*)(smem + OFF_MASK);

    int tid = threadIdx.x;
    int wid = tid >> 5, l = tid & 31;
    int lr = l >> 2, lc = l & 3;
    int lr8 = l & 7, lg = (l >> 3) & 1, kg4 = l >> 4;
    int wm = wid >> 2, wn = wid & 3;

    int qt = blockIdx.x, h = blockIdx.y, b = blockIdx.z;
    int q0 = qt * QT;
    size_t bh_ = (size_t)b * HH + h;
    const float* Qp = Q + (bh_ * SDIM + q0) * DDIM;
    const float* Kp = K + bh_ * SDIM * DDIM;
    const float* Vp = V + bh_ * SDIM * DDIM;
    const float* Mp = mask + (size_t)b * SDIM;
    const float* Cp = g_C + ((size_t)b * SDIM + q0) * SDIM;
    float* Op = Og + (bh_ * SDIM + q0) * DDIM;
    float* Pp = Pg + (bh_ * SDIM + q0) * SDIM;

    sMask[tid] = Mp[tid];

    // ---- Q (x 1/8) -> hi/lo bf16 smem ----
    {
        const float4* Q4 = (const float4*)Qp;
        #pragma unroll
        for (int t = 0; t < 2; ++t) {
            int idx = tid + 512 * t;
            float4 f = Q4[idx];
            int r = idx >> 4, c = (idx & 15) << 2;
            float v0 = f.x * 0.125f, v1 = f.y * 0.125f, v2 = f.z * 0.125f, v3 = f.w * 0.125f;
            char* dst = smem + OFF_QS + r * KSTRB + 2 * c;
            *(uint2*)dst = make_uint2(packbf(v0, v1), packbf(v2, v3));
            *(uint2*)(dst + 9216) = make_uint2(
                packbf(v0 - bfround(v0), v1 - bfround(v1)),
                packbf(v2 - bfround(v2), v3 - bfround(v3)));
        }
    }
    // ---- K tile 0 -> buf0; prefetch tile 1 ----
    {
        const float4* K4 = (const float4*)Kp;
        #pragma unroll
        for (int t = 0; t < 2; ++t) {
            int idx = tid + 512 * t;
            float4 f = K4[idx];
            int r = idx >> 4, c = (idx & 15) << 2;
            char* dst = smem + OFF_K + r * KSTRB + 2 * c;
            *(uint2*)dst = make_uint2(packbf(f.x, f.y), packbf(f.z, f.w));
            *(uint2*)(dst + 9216) = make_uint2(
                packbf(f.x - bfround(f.x), f.y - bfround(f.y)),
                packbf(f.z - bfround(f.z), f.w - bfround(f.w)));
        }
    }
    float4 pf[2];
    {
        const float4* K4 = (const float4*)(Kp + 4096);
        pf[0] = K4[tid]; pf[1] = K4[tid + 512];
    }
    __syncthreads();

    // ---- resident Q fragments ----
    uint32_t qah[4][4], qal[4][4];
    {
        uint32_t ra = sb + OFF_QS + (16 * wm + lr8 + 8 * lg) * KSTRB + 16 * kg4;
        #pragma unroll
        for (int ks = 0; ks < 4; ++ks) {
            ldm_x4(qah[ks], ra + ks * 32);
            ldm_x4(qal[ks], ra + 9216 + ks * 32);
        }
    }

    // ---- Phase 1: scores (regs) + V staging interleaved ----
    const float4* V4 = (const float4*)Vp;
    float sc[8][2][4];
    #pragma unroll
    for (int kt = 0; kt < 8; ++kt) {
        // V chunk LDGs for this iteration (latency covered by mma block)
        float4 vf0 = V4[tid + 512 * (2 * kt)];
        float4 vf1 = V4[tid + 512 * (2 * kt + 1)];

        #pragma unroll
        for (int nf = 0; nf < 2; ++nf)
            #pragma unroll
            for (int e = 0; e < 4; ++e) sc[kt][nf][e] = 0.0f;

        uint32_t rbase = sb + OFF_K + (kt & 1) * 18432
                         + (16 * wn + lr8 + 8 * kg4) * KSTRB + 16 * lg;
        uint32_t bh[2][4];
        ldm_x4(bh[0], rbase);
        #pragma unroll
        for (int ks = 0; ks < 4; ++ks) {
            int cc = ks & 1;
            if (ks < 3) ldm_x4(bh[cc ^ 1], rbase + 32 * (ks + 1));
            uint32_t bl[4];
            ldm_x4(bl, rbase + 9216 + 32 * ks);
            #pragma unroll
            for (int nf = 0; nf < 2; ++nf) {
                mma_bf16(sc[kt][nf], qah[ks], bh[cc] + 2 * nf);
                mma_bf16(sc[kt][nf], qal[ks], bh[cc] + 2 * nf);
                mma_bf16(sc[kt][nf], qah[ks], bl + 2 * nf);
            }
        }
        if (kt < 7) {
            #pragma unroll
            for (int t = 0; t < 2; ++t) {
                int idx = tid + 512 * t;
                float4 f = pf[t];
                int r = idx >> 4, c = (idx & 15) << 2;
                char* dst = smem + OFF_K + ((kt + 1) & 1) * 18432 + r * KSTRB + 2 * c;
                *(uint2*)dst = make_uint2(packbf(f.x, f.y), packbf(f.z, f.w));
                *(uint2*)(dst + 9216) = make_uint2(
                    packbf(f.x - bfround(f.x), f.y - bfround(f.y)),
                    packbf(f.z - bfround(f.z), f.w - bfround(f.w)));
            }
            __syncthreads();
            if (kt < 6) {
                const float4* K4 = (const float4*)(Kp + (size_t)(kt + 2) * 4096);
                pf[0] = K4[tid]; pf[1] = K4[tid + 512];
            }
        }
        // V chunk STS (region disjoint from K buffers; consumed after RS barrier)
        {
            int idx = tid + 512 * (2 * kt);
            int r = idx >> 4, c = (idx & 15) << 2;
            char* dst = smem + OFF_V + r * KSTRB + 2 * c;
            *(uint2*)dst = make_uint2(packbf(vf0.x, vf0.y), packbf(vf0.z, vf0.w));
            *(uint2*)(dst + 73728) = make_uint2(
                packbf(vf0.x - bfround(vf0.x), vf0.y - bfround(vf0.y)),
                packbf(vf0.z - bfround(vf0.z), vf0.w - bfround(vf0.w)));
            idx += 512;
            r = idx >> 4; c = (idx & 15) << 2;
            dst = smem + OFF_V + r * KSTRB + 2 * c;
            *(uint2*)dst = make_uint2(packbf(vf1.x, vf1.y), packbf(vf1.z, vf1.w));
            *(uint2*)(dst + 73728) = make_uint2(
                packbf(vf1.x - bfround(vf1.x), vf1.y - bfround(vf1.y)),
                packbf(vf1.z - bfround(vf1.z), vf1.w - bfround(vf1.w)));
        }
    }

    // ---- softmax reductions (scores stay in regs) ----
    int r0 = 16 * wm + lr, r1 = r0 + 8;
    {
        float2 mk;
        #pragma unroll
        for (int j = 0; j < 8; ++j)
            #pragma unroll
            for (int nf = 0; nf < 2; ++nf) {
                mk = *(float2*)(smem + OFF_MASK + 4 * (64 * j + 16 * wn + 8 * nf + 2 * lc));
                if (mk.x == 0.0f) { sc[j][nf][0] = -1e12f; sc[j][nf][2] = -1e12f; }
                if (mk.y == 0.0f) { sc[j][nf][1] = -1e12f; sc[j][nf][3] = -1e12f; }
            }
    }
    float mx0 = -CUDART_INF_F, mx1 = -CUDART_INF_F;
    #pragma unroll
    for (int j = 0; j < 8; ++j)
        #pragma unroll
        for (int nf = 0; nf < 2; ++nf) {
            mx0 = fmaxf(mx0, fmaxf(sc[j][nf][0], sc[j][nf][1]));
            mx1 = fmaxf(mx1, fmaxf(sc[j][nf][2], sc[j][nf][3]));
        }
    #pragma unroll
    for (int o = 1; o < 4; o <<= 1) {
        mx0 = fmaxf(mx0, __shfl_xor_sync(0xffffffffu, mx0, o));
        mx1 = fmaxf(mx1, __shfl_xor_sync(0xffffffffu, mx1, o));
    }
    if (lc == 0) {
        ((float*)(smem + OFF_RM))[r0 * 4 + wn] = mx0;
        ((float*)(smem + OFF_RM))[r1 * 4 + wn] = mx1;
    }
    __syncthreads();
    {
        float4 m0 = *(float4*)(smem + OFF_RM + r0 * 16);
        float4 m1 = *(float4*)(smem + OFF_RM + r1 * 16);
        mx0 = fmaxf(fmaxf(m0.x, m0.y), fmaxf(m0.z, m0.w));
        mx1 = fmaxf(fmaxf(m1.x, m1.y), fmaxf(m1.z, m1.w));
    }
    float s0 = 0.0f, s1 = 0.0f;
    #pragma unroll
    for (int j = 0; j < 8; ++j)
        #pragma unroll
        for (int nf = 0; nf < 2; ++nf) {
            sc[j][nf][0] = __expf(sc[j][nf][0] - mx0);
            sc[j][nf][1] = __expf(sc[j][nf][1] - mx0);
            sc[j][nf][2] = __expf(sc[j][nf][2] - mx1);
            sc[j][nf][3] = __expf(sc[j][nf][3] - mx1);
            s0 += sc[j][nf][0] + sc[j][nf][1];
            s1 += sc[j][nf][2] + sc[j][nf][3];
        }
    #pragma unroll
    for (int o = 1; o < 4; o <<= 1) {
        s0 += __shfl_xor_sync(0xffffffffu, s0, o);
        s1 += __shfl_xor_sync(0xffffffffu, s1, o);
    }
    if (lc == 0) {
        ((float*)(smem + OFF_RS))[r0 * 4 + wn] = s0;
        ((float*)(smem + OFF_RS))[r1 * 4 + wn] = s1;
    }

    // prefetch first C chunk while waiting on the sum barrier
    int colb = 16 * wn + 2 * lc;
    float2 cb[2][2][2];
    #pragma unroll
    for (int nf = 0; nf < 2; ++nf) {
        cb[0][0][nf] = __ldg((const float2*)(Cp + (size_t)r0 * SDIM + colb + 8 * nf));
        cb[0][1][nf] = __ldg((const float2*)(Cp + (size_t)r1 * SDIM + colb + 8 * nf));
    }
    __syncthreads();
    float inv0, inv1;
    {
        float4 t0 = *(float4*)(smem + OFF_RS + r0 * 16);
        float4 t1 = *(float4*)(smem + OFF_RS + r1 * 16);
        inv0 = 1.0f / (t0.x + t0.y + t0.z + t0.w);
        inv1 = 1.0f / (t1.x + t1.y + t1.z + t1.w);
    }

    // ---- fused phase 2+3 per 64-key chunk j, C prefetched, V frags pipelined ----
    float accO[8][4];
    #pragma unroll
    for (int nj = 0; nj < 8; ++nj)
        #pragma unroll
        for (int e = 0; e < 4; ++e) accO[nj][e] = 0.0f;

    #pragma unroll
    for (int j = 0; j < 8; ++j) {
        int cur = j & 1, nxt = cur ^ 1;
        if (j < 7) {
            int coln = 64 * (j + 1) + colb;
            #pragma unroll
            for (int nf = 0; nf < 2; ++nf) {
                cb[nxt][0][nf] = __ldg((const float2*)(Cp + (size_t)r0 * SDIM + coln + 8 * nf));
                cb[nxt][1][nf] = __ldg((const float2*)(Cp + (size_t)r1 * SDIM + coln + 8 * nf));
            }
        }
        uint32_t wah[4], wal[4];
        #pragma unroll
        for (int nf = 0; nf < 2; ++nf) {
            int col = 64 * j + colb + 8 * nf;
            float p00 = sc[j][nf][0] * inv0, p01 = sc[j][nf][1] * inv0;
            float p10 = sc[j][nf][2] * inv1, p11 = sc[j][nf][3] * inv1;
            __stcs((float2*)(Pp + (size_t)r0 * SDIM + col), make_float2(p00, p01));
            __stcs((float2*)(Pp + (size_t)r1 * SDIM + col), make_float2(p10, p11));
            float w00 = fmaf(L_ATT, p00, cb[cur][0][nf].x);
            float w01 = fmaf(L_ATT, p01, cb[cur][0][nf].y);
            float w10 = fmaf(L_ATT, p10, cb[cur][1][nf].x);
            float w11 = fmaf(L_ATT, p11, cb[cur][1][nf].y);
            wah[2 * nf]     = packbf(w00, w01);
            wah[2 * nf + 1] = packbf(w10, w11);
            wal[2 * nf]     = packbf(w00 - bfround(w00), w01 - bfround(w01));
            wal[2 * nf + 1] = packbf(w10 - bfround(w10), w11 - bfround(w11));
        }

        uint32_t vrow = sb + OFF_V + (64 * j + 16 * wn + lr8 + 8 * lg) * KSTRB + 73728 * kg4;
        uint32_t vb[2][4];
        ldm_x4t(vb[0], vrow);
        #pragma unroll
        for (int nj = 0; nj < 8; ++nj) {
            int vc = nj & 1;
            if (nj < 7) ldm_x4t(vb[vc ^ 1], vrow + 16 * (nj + 1));
            mma_bf16(accO[nj], wah, vb[vc]);
            mma_bf16(accO[nj], wal, vb[vc]);
            mma_bf16(accO[nj], wah, vb[vc] + 2);
        }
    }

    // ---- parallel reduction: 4 disjoint regions, one barrier ----
    __syncthreads();   // all reads of Q/K smem regions complete (phase 1 done long ago)
    {
        static const int REDB[4] = {REDB0, REDB1, REDB2, REDB3};
        char* reg_ = smem + REDB[wn];
        #pragma unroll
        for (int nj = 0; nj < 8; ++nj) {
            int col = 8 * nj + 2 * lc;
            *(float2*)(reg_ + (r0 * RSTR + col) * 4) = make_float2(accO[nj][0], accO[nj][1]);
            *(float2*)(reg_ + (r1 * RSTR + col) * 4) = make_float2(accO[nj][2], accO[nj][3]);
        }
    }
    __syncthreads();

    #pragma unroll
    for (int t = 0; t < 2; ++t) {
        int idx = tid + 512 * t;
        int row = idx >> 4, c0 = (idx & 15) << 2;
        float4 a0 = *(float4*)(smem + REDB0 + (row * RSTR + c0) * 4);
        float4 a1 = *(float4*)(smem + REDB1 + (row * RSTR + c0) * 4);
        float4 a2 = *(float4*)(smem + REDB2 + (row * RSTR + c0) * 4);
        float4 a3 = *(float4*)(smem + REDB3 + (row * RSTR + c0) * 4);
        float4 o;
        o.x = (a0.x + a1.x) + (a2.x + a3.x);
        o.y = (a0.y + a1.y) + (a2.y + a3.y);
        o.z = (a0.z + a1.z) + (a2.z + a3.z);
        o.w = (a0.w + a1.w) + (a2.w + a3.w);
        *(float4*)(Op + row * DDIM + c0) = o;
    }
}

extern "C" void kernel_launch(void* const* d_in, const int* in_sizes, int n_in,
                              void* d_out, int out_size)
{
    const float* Q    = (const float*)d_in[0];
    const float* K    = (const float*)d_in[1];
    const float* V    = (const float*)d_in[2];
    const float* mask = (const float*)d_in[3];
    const float* adj  = (const float*)d_in[4];
    const float* dist = (const float*)d_in[5];

    float* outp  = (float*)d_out;
    float* pattn = outp + (size_t)BB * HH * SDIM * DDIM;

    precompute_C_kernel<<<BB * SDIM, 256>>>(adj, dist, mask);

    cudaFuncSetAttribute(attn_mma_kernel,
                         cudaFuncAttributeMaxDynamicSharedMemorySize, SMEM_BYTES);
    dim3 grid(SDIM / QT, HH, BB);
    attn_mma_kernel<<<grid, THREADS, SMEM_BYTES>>>(Q, K, V, mask, outp, pattn);
}

// round 12
// speedup vs baseline: 1.0164x; 1.0146x over previous
#include <cuda_runtime.h>
#include <cuda_bf16.h>
#include <math_constants.h>
#include <cstdint>

#define BB 16
#define HH 16
#define SDIM 512
#define DDIM 64
#define QT 32
#define THREADS 256
#define KSTRB 144

#define L_ATT 0.33f
#define L_DIST 0.33f
#define L_ADJ (1.0f - 0.33f - 0.33f)

// ---- smem map (bytes) ----
#define OFF_QS   0          // Q hi 32x144, lo at +4608
#define QLO_OFF  4608
#define OFF_K    9216       // 2 bufs x (hi 9216 + lo 9216) — K in phase 1, V chunks in phase 3
#define OFF_RED  46080      // 4th reduction region
#define RSTR     68
#define OFF_RM   54784
#define OFF_RS   55296
#define OFF_MASK 55808
#define SMEM_BYTES 57856
#define REDB0 0
#define REDB1 9216
#define REDB2 27648
#define REDB3 46080

__device__ float g_C[(size_t)BB * SDIM * SDIM];

__global__ __launch_bounds__(256) void precompute_C_kernel(
    const float* __restrict__ adj, const float* __restrict__ dist,
    const float* __restrict__ mask)
{
    int row = blockIdx.x;
    int b = row >> 9;
    const float* arow = adj  + (size_t)row * SDIM;
    const float* drow = dist + (size_t)row * SDIM;
    const float* mrow = mask + (size_t)b * SDIM;
    float* crow = g_C + (size_t)row * SDIM;
    int tid = threadIdx.x, w = tid >> 5, l = tid & 31;

    float a0 = arow[tid], a1 = arow[tid + 256];
    float d0 = drow[tid], d1 = drow[tid + 256];
    float m0 = mrow[tid], m1 = mrow[tid + 256];
    float x0 = (m0 == 0.0f) ? -CUDART_INF_F : -d0;
    float x1 = (m1 == 0.0f) ? -CUDART_INF_F : -d1;

    float asum = a0 + a1, xmax = fmaxf(x0, x1);
    #pragma unroll
    for (int o = 16; o > 0; o >>= 1) {
        asum += __shfl_xor_sync(0xffffffffu, asum, o);
        xmax = fmaxf(xmax, __shfl_xor_sync(0xffffffffu, xmax, o));
    }
    __shared__ float rs[8], rm[8], re[8];
    if (l == 0) { rs[w] = asum; rm[w] = xmax; }
    __syncthreads();
    float ts = 0.0f, tm = -CUDART_INF_F;
    #pragma unroll
    for (int i = 0; i < 8; i++) { ts += rs[i]; tm = fmaxf(tm, rm[i]); }

    float e0 = __expf(x0 - tm), e1 = __expf(x1 - tm), es = e0 + e1;
    #pragma unroll
    for (int o = 16; o > 0; o >>= 1) es += __shfl_xor_sync(0xffffffffu, es, o);
    if (l == 0) re[w] = es;
    __syncthreads();
    float te = 0.0f;
    #pragma unroll
    for (int i = 0; i < 8; i++) te += re[i];

    float inv_a = 1.0f / (ts + 1e-6f), inv_e = 1.0f / te;
    crow[tid]       = L_DIST * e0 * inv_e + L_ADJ * a0 * inv_a;
    crow[tid + 256] = L_DIST * e1 * inv_e + L_ADJ * a1 * inv_a;
}

__device__ __forceinline__ void mma_bf16(float* c, const uint32_t* a, const uint32_t* b) {
    asm volatile("mma.sync.aligned.m16n8k16.row.col.f32.bf16.bf16.f32 "
        "{%0,%1,%2,%3}, {%4,%5,%6,%7}, {%8,%9}, {%0,%1,%2,%3};"
        : "+f"(c[0]), "+f"(c[1]), "+f"(c[2]), "+f"(c[3])
        : "r"(a[0]), "r"(a[1]), "r"(a[2]), "r"(a[3]), "r"(b[0]), "r"(b[1]));
}
__device__ __forceinline__ void ldm_x4(uint32_t* r, uint32_t a) {
    asm volatile("ldmatrix.sync.aligned.m8n8.x4.shared.b16 {%0,%1,%2,%3}, [%4];"
        : "=r"(r[0]), "=r"(r[1]), "=r"(r[2]), "=r"(r[3]) : "r"(a));
}
__device__ __forceinline__ void ldm_x4t(uint32_t* r, uint32_t a) {
    asm volatile("ldmatrix.sync.aligned.m8n8.x4.trans.shared.b16 {%0,%1,%2,%3}, [%4];"
        : "=r"(r[0]), "=r"(r[1]), "=r"(r[2]), "=r"(r[3]) : "r"(a));
}
__device__ __forceinline__ uint32_t smem_u32(const void* p) {
    uint32_t a;
    asm("{ .reg .u64 t; cvta.to.shared.u64 t, %1; cvt.u32.u64 %0, t; }" : "=r"(a) : "l"(p));
    return a;
}
__device__ __forceinline__ uint32_t packbf(float lo, float hi) {
    uint32_t r;
    asm("cvt.rn.bf16x2.f32 %0, %1, %2;" : "=r"(r) : "f"(hi), "f"(lo));
    return r;
}
__device__ __forceinline__ float bfround(float x) {
    return __bfloat162float(__float2bfloat16_rn(x));
}

__global__ __launch_bounds__(256, 2) void attn_mma_kernel(
    const float* __restrict__ Q, const float* __restrict__ K,
    const float* __restrict__ V, const float* __restrict__ mask,
    float* __restrict__ Og, float* __restrict__ Pg)
{
    extern __shared__ char smem[];
    uint32_t sb = smem_u32(smem);
    float* sMask = (float*)(smem + OFF_MASK);

    int tid = threadIdx.x;
    int wid = tid >> 5, l = tid & 31;
    int lr = l >> 2, lc = l & 3;
    int lr8 = l & 7, lg = (l >> 3) & 1, kg4 = l >> 4;
    int wm = wid >> 2, wn = wid & 3;   // m2 x n4

    int qt = blockIdx.x, h = blockIdx.y, b = blockIdx.z;
    int q0 = qt * QT;
    size_t bh_ = (size_t)b * HH + h;
    const float* Qp = Q + (bh_ * SDIM + q0) * DDIM;
    const float* Kp = K + bh_ * SDIM * DDIM;
    const float* Vp = V + bh_ * SDIM * DDIM;
    const float* Mp = mask + (size_t)b * SDIM;
    const float* Cp = g_C + ((size_t)b * SDIM + q0) * SDIM;
    float* Op = Og + (bh_ * SDIM + q0) * DDIM;
    float* Pp = Pg + (bh_ * SDIM + q0) * SDIM;

    sMask[tid] = Mp[tid];
    sMask[tid + 256] = Mp[tid + 256];

    // ---- Q (x 1/8) -> hi/lo bf16 smem (32x64) ----
    {
        const float4* Q4 = (const float4*)Qp;
        #pragma unroll
        for (int t = 0; t < 2; ++t) {
            int idx = tid + 256 * t;
            float4 f = Q4[idx];
            int r = idx >> 4, c = (idx & 15) << 2;
            float v0 = f.x * 0.125f, v1 = f.y * 0.125f, v2 = f.z * 0.125f, v3 = f.w * 0.125f;
            char* dst = smem + OFF_QS + r * KSTRB + 2 * c;
            *(uint2*)dst = make_uint2(packbf(v0, v1), packbf(v2, v3));
            *(uint2*)(dst + QLO_OFF) = make_uint2(
                packbf(v0 - bfround(v0), v1 - bfround(v1)),
                packbf(v2 - bfround(v2), v3 - bfround(v3)));
        }
    }
    // ---- K tile 0 -> buf0; prefetch tile 1 ----
    {
        const float4* K4 = (const float4*)Kp;
        #pragma unroll
        for (int t = 0; t < 4; ++t) {
            int idx = tid + 256 * t;
            float4 f = K4[idx];
            int r = idx >> 4, c = (idx & 15) << 2;
            char* dst = smem + OFF_K + r * KSTRB + 2 * c;
            *(uint2*)dst = make_uint2(packbf(f.x, f.y), packbf(f.z, f.w));
            *(uint2*)(dst + 9216) = make_uint2(
                packbf(f.x - bfround(f.x), f.y - bfround(f.y)),
                packbf(f.z - bfround(f.z), f.w - bfround(f.w)));
        }
    }
    float4 pf[4];
    {
        const float4* K4 = (const float4*)(Kp + 4096);
        #pragma unroll
        for (int t = 0; t < 4; ++t) pf[t] = K4[tid + 256 * t];
    }
    __syncthreads();

    // ---- resident Q fragments (rows 16*wm..+15) ----
    uint32_t qah[4][4], qal[4][4];
    {
        uint32_t ra = sb + OFF_QS + (16 * wm + lr8 + 8 * lg) * KSTRB + 16 * kg4;
        #pragma unroll
        for (int ks = 0; ks < 4; ++ks) {
            ldm_x4(qah[ks], ra + ks * 32);
            ldm_x4(qal[ks], ra + QLO_OFF + ks * 32);
        }
    }

    // ---- Phase 1: scores (regs), double-buffered K ----
    float sc[8][2][4];
    #pragma unroll
    for (int kt = 0; kt < 8; ++kt) {
        #pragma unroll
        for (int nf = 0; nf < 2; ++nf)
            #pragma unroll
            for (int e = 0; e < 4; ++e) sc[kt][nf][e] = 0.0f;

        uint32_t rbase = sb + OFF_K + (kt & 1) * 18432
                         + (16 * wn + lr8 + 8 * kg4) * KSTRB + 16 * lg;
        uint32_t bh[2][4];
        ldm_x4(bh[0], rbase);
        #pragma unroll
        for (int ks = 0; ks < 4; ++ks) {
            int cc = ks & 1;
            if (ks < 3) ldm_x4(bh[cc ^ 1], rbase + 32 * (ks + 1));
            uint32_t bl[4];
            ldm_x4(bl, rbase + 9216 + 32 * ks);
            #pragma unroll
            for (int nf = 0; nf < 2; ++nf) {
                mma_bf16(sc[kt][nf], qah[ks], bh[cc] + 2 * nf);
                mma_bf16(sc[kt][nf], qal[ks], bh[cc] + 2 * nf);
                mma_bf16(sc[kt][nf], qah[ks], bl + 2 * nf);
            }
        }
        if (kt < 7) {
            #pragma unroll
            for (int t = 0; t < 4; ++t) {
                int idx = tid + 256 * t;
                float4 f = pf[t];
                int r = idx >> 4, c = (idx & 15) << 2;
                char* dst = smem + OFF_K + ((kt + 1) & 1) * 18432 + r * KSTRB + 2 * c;
                *(uint2*)dst = make_uint2(packbf(f.x, f.y), packbf(f.z, f.w));
                *(uint2*)(dst + 9216) = make_uint2(
                    packbf(f.x - bfround(f.x), f.y - bfround(f.y)),
                    packbf(f.z - bfround(f.z), f.w - bfround(f.w)));
            }
            __syncthreads();
            if (kt < 6) {
                const float4* K4 = (const float4*)(Kp + (size_t)(kt + 2) * 4096);
                #pragma unroll
                for (int t = 0; t < 4; ++t) pf[t] = K4[tid + 256 * t];
            }
        }
    }

    // ---- V chunk 0 LDG (latency hidden by softmax math) ----
    const float4* V4 = (const float4*)Vp;
    float4 vf[4];
    #pragma unroll
    for (int t = 0; t < 4; ++t) vf[t] = V4[tid + 256 * t];

    // ---- softmax: mask + row max ----
    int r0 = 16 * wm + lr, r1 = r0 + 8;
    {
        float2 mk;
        #pragma unroll
        for (int j = 0; j < 8; ++j)
            #pragma unroll
            for (int nf = 0; nf < 2; ++nf) {
                mk = *(float2*)(smem + OFF_MASK + 4 * (64 * j + 16 * wn + 8 * nf + 2 * lc));
                if (mk.x == 0.0f) { sc[j][nf][0] = -1e12f; sc[j][nf][2] = -1e12f; }
                if (mk.y == 0.0f) { sc[j][nf][1] = -1e12f; sc[j][nf][3] = -1e12f; }
            }
    }
    float mx0 = -CUDART_INF_F, mx1 = -CUDART_INF_F;
    #pragma unroll
    for (int j = 0; j < 8; ++j)
        #pragma unroll
        for (int nf = 0; nf < 2; ++nf) {
            mx0 = fmaxf(mx0, fmaxf(sc[j][nf][0], sc[j][nf][1]));
            mx1 = fmaxf(mx1, fmaxf(sc[j][nf][2], sc[j][nf][3]));
        }
    #pragma unroll
    for (int o = 1; o < 4; o <<= 1) {
        mx0 = fmaxf(mx0, __shfl_xor_sync(0xffffffffu, mx0, o));
        mx1 = fmaxf(mx1, __shfl_xor_sync(0xffffffffu, mx1, o));
    }
    if (lc == 0) {
        ((float*)(smem + OFF_RM))[r0 * 4 + wn] = mx0;
        ((float*)(smem + OFF_RM))[r1 * 4 + wn] = mx1;
    }
    // STS V chunk 0 -> buf0 (buf0 dead since kt6->7 barrier)
    #pragma unroll
    for (int t = 0; t < 4; ++t) {
        int idx = tid + 256 * t;
        float4 f = vf[t];
        int r = idx >> 4, c = (idx & 15) << 2;
        char* dst = smem + OFF_K + r * KSTRB + 2 * c;
        *(uint2*)dst = make_uint2(packbf(f.x, f.y), packbf(f.z, f.w));
        *(uint2*)(dst + 9216) = make_uint2(
            packbf(f.x - bfround(f.x), f.y - bfround(f.y)),
            packbf(f.z - bfround(f.z), f.w - bfround(f.w)));
    }
    __syncthreads();
    {
        float4 m0 = *(float4*)(smem + OFF_RM + r0 * 16);
        float4 m1 = *(float4*)(smem + OFF_RM + r1 * 16);
        mx0 = fmaxf(fmaxf(m0.x, m0.y), fmaxf(m0.z, m0.w));
        mx1 = fmaxf(fmaxf(m1.x, m1.y), fmaxf(m1.z, m1.w));
    }
    float s0 = 0.0f, s1 = 0.0f;
    #pragma unroll
    for (int j = 0; j < 8; ++j)
        #pragma unroll
        for (int nf = 0; nf < 2; ++nf) {
            sc[j][nf][0] = __expf(sc[j][nf][0] - mx0);
            sc[j][nf][1] = __expf(sc[j][nf][1] - mx0);
            sc[j][nf][2] = __expf(sc[j][nf][2] - mx1);
            sc[j][nf][3] = __expf(sc[j][nf][3] - mx1);
            s0 += sc[j][nf][0] + sc[j][nf][1];
            s1 += sc[j][nf][2] + sc[j][nf][3];
        }
    #pragma unroll
    for (int o = 1; o < 4; o <<= 1) {
        s0 += __shfl_xor_sync(0xffffffffu, s0, o);
        s1 += __shfl_xor_sync(0xffffffffu, s1, o);
    }
    if (lc == 0) {
        ((float*)(smem + OFF_RS))[r0 * 4 + wn] = s0;
        ((float*)(smem + OFF_RS))[r1 * 4 + wn] = s1;
    }
    // LDG V chunk 1 + first C chunk while the sum barrier drains
    #pragma unroll
    for (int t = 0; t < 4; ++t) vf[t] = V4[1024 + tid + 256 * t];
    int colb = 16 * wn + 2 * lc;
    float2 cb[2][2][2];
    #pragma unroll
    for (int nf = 0; nf < 2; ++nf) {
        cb[0][0][nf] = __ldg((const float2*)(Cp + (size_t)r0 * SDIM + colb + 8 * nf));
        cb[0][1][nf] = __ldg((const float2*)(Cp + (size_t)r1 * SDIM + colb + 8 * nf));
    }
    __syncthreads();
    float inv0, inv1;
    {
        float4 t0 = *(float4*)(smem + OFF_RS + r0 * 16);
        float4 t1 = *(float4*)(smem + OFF_RS + r1 * 16);
        inv0 = 1.0f / (t0.x + t0.y + t0.z + t0.w);
        inv1 = 1.0f / (t1.x + t1.y + t1.z + t1.w);
    }

    // ---- fused phase 2+3 per 64-key chunk j; V streamed through K buffers ----
    float accO[8][4];
    #pragma unroll
    for (int nj = 0; nj < 8; ++nj)
        #pragma unroll
        for (int e = 0; e < 4; ++e) accO[nj][e] = 0.0f;

    #pragma unroll
    for (int j = 0; j < 8; ++j) {
        int cur = j & 1, nxt = cur ^ 1;
        if (j < 7) {
            int coln = 64 * (j + 1) + colb;
            #pragma unroll
            for (int nf = 0; nf < 2; ++nf) {
                cb[nxt][0][nf] = __ldg((const float2*)(Cp + (size_t)r0 * SDIM + coln + 8 * nf));
                cb[nxt][1][nf] = __ldg((const float2*)(Cp + (size_t)r1 * SDIM + coln + 8 * nf));
            }
        }
        uint32_t wah[4], wal[4];
        #pragma unroll
        for (int nf = 0; nf < 2; ++nf) {
            int col = 64 * j + colb + 8 * nf;
            float p00 = sc[j][nf][0] * inv0, p01 = sc[j][nf][1] * inv0;
            float p10 = sc[j][nf][2] * inv1, p11 = sc[j][nf][3] * inv1;
            __stcs((float2*)(Pp + (size_t)r0 * SDIM + col), make_float2(p00, p01));
            __stcs((float2*)(Pp + (size_t)r1 * SDIM + col), make_float2(p10, p11));
            float w00 = fmaf(L_ATT, p00, cb[cur][0][nf].x);
            float w01 = fmaf(L_ATT, p01, cb[cur][0][nf].y);
            float w10 = fmaf(L_ATT, p10, cb[cur][1][nf].x);
            float w11 = fmaf(L_ATT, p11, cb[cur][1][nf].y);
            wah[2 * nf]     = packbf(w00, w01);
            wah[2 * nf + 1] = packbf(w10, w11);
            wal[2 * nf]     = packbf(w00 - bfround(w00), w01 - bfround(w01));
            wal[2 * nf + 1] = packbf(w10 - bfround(w10), w11 - bfround(w11));
        }

        uint32_t vrow = sb + OFF_K + cur * 18432
                        + (16 * wn + lr8 + 8 * lg) * KSTRB + 9216 * kg4;
        uint32_t vb[2][4];
        ldm_x4t(vb[0], vrow);
        #pragma unroll
        for (int nj = 0; nj < 8; ++nj) {
            int vc = nj & 1;
            if (nj < 7) ldm_x4t(vb[vc ^ 1], vrow + 16 * (nj + 1));
            mma_bf16(accO[nj], wah, vb[vc]);
            mma_bf16(accO[nj], wal, vb[vc]);
            mma_bf16(accO[nj], wah, vb[vc] + 2);
        }

        if (j < 7) {
            // STS V chunk j+1 -> other buf (dead since end of j-1), then barrier
            #pragma unroll
            for (int t = 0; t < 4; ++t) {
                int idx = tid + 256 * t;
                float4 f = vf[t];
                int r = idx >> 4, c = (idx & 15) << 2;
                char* dst = smem + OFF_K + nxt * 18432 + r * KSTRB + 2 * c;
                *(uint2*)dst = make_uint2(packbf(f.x, f.y), packbf(f.z, f.w));
                *(uint2*)(dst + 9216) = make_uint2(
                    packbf(f.x - bfround(f.x), f.y - bfround(f.y)),
                    packbf(f.z - bfround(f.z), f.w - bfround(f.w)));
            }
            __syncthreads();
            if (j < 6) {
                #pragma unroll
                for (int t = 0; t < 4; ++t)
                    vf[t] = V4[(size_t)(j + 2) * 1024 + tid + 256 * t];
            }
        }
    }

    // ---- parallel reduction: 4 disjoint regions, one barrier ----
    __syncthreads();
    {
        static const int REDB[4] = {REDB0, REDB1, REDB2, REDB3};
        char* reg_ = smem + REDB[wn];
        #pragma unroll
        for (int nj = 0; nj < 8; ++nj) {
            int col = 8 * nj + 2 * lc;
            *(float2*)(reg_ + (r0 * RSTR + col) * 4) = make_float2(accO[nj][0], accO[nj][1]);
            *(float2*)(reg_ + (r1 * RSTR + col) * 4) = make_float2(accO[nj][2], accO[nj][3]);
        }
    }
    __syncthreads();

    #pragma unroll
    for (int t = 0; t < 2; ++t) {
        int idx = tid + 256 * t;
        int row = idx >> 4, c0 = (idx & 15) << 2;
        float4 a0 = *(float4*)(smem + REDB0 + (row * RSTR + c0) * 4);
        float4 a1 = *(float4*)(smem + REDB1 + (row * RSTR + c0) * 4);
        float4 a2 = *(float4*)(smem + REDB2 + (row * RSTR + c0) * 4);
        float4 a3 = *(float4*)(smem + REDB3 + (row * RSTR + c0) * 4);
        float4 o;
        o.x = (a0.x + a1.x) + (a2.x + a3.x);
        o.y = (a0.y + a1.y) + (a2.y + a3.y);
        o.z = (a0.z + a1.z) + (a2.z + a3.z);
        o.w = (a0.w + a1.w) + (a2.w + a3.w);
        *(float4*)(Op + row * DDIM + c0) = o;
    }
}

extern "C" void kernel_launch(void* const* d_in, const int* in_sizes, int n_in,
                              void* d_out, int out_size)
{
    const float* Q    = (const float*)d_in[0];
    const float* K    = (const float*)d_in[1];
    const float* V    = (const float*)d_in[2];
    const float* mask = (const float*)d_in[3];
    const float* adj  = (const float*)d_in[4];
    const float* dist = (const float*)d_in[5];

    float* outp  = (float*)d_out;
    float* pattn = outp + (size_t)BB * HH * SDIM * DDIM;

    precompute_C_kernel<<<BB * SDIM, 256>>>(adj, dist, mask);

    cudaFuncSetAttribute(attn_mma_kernel,
                         cudaFuncAttributeMaxDynamicSharedMemorySize, SMEM_BYTES);
    dim3 grid(SDIM / QT, HH, BB);
    attn_mma_kernel<<<grid, THREADS, SMEM_BYTES>>>(Q, K, V, mask, outp, pattn);
}

// round 13
// speedup vs baseline: 1.0435x; 1.0267x over previous
#include <cuda_runtime.h>
#include <cuda_bf16.h>
#include <math_constants.h>
#include <cstdint>

#define BB 16
#define HH 16
#define SDIM 512
#define DDIM 64
#define QT 64
#define THREADS 512
#define KSTRB 144

#define L_ATT 0.33f
#define L_DIST 0.33f
#define L_ADJ (1.0f - 0.33f - 0.33f)

// ---- smem map (bytes) ----
#define OFF_QS   0          // Q hi 64x144, lo at +9216 (18432)
#define OFF_K    18432      // 2 bufs x (hi 9216 + lo 9216); V chunks stream here in phase 3
#define RSTR     68
#define OFF_RED3 55296      // 4th reduction region (17408)
#define OFF_RM   72704
#define OFF_RS   73728
#define OFF_MASK 74752
#define SMEM_BYTES 76800
#define REDB0 0             // Q region (dead after phase-1 frag loads)
#define REDB1 18432         // K buf0
#define REDB2 36864         // K buf1
#define REDB3 OFF_RED3

__device__ float g_C[(size_t)BB * SDIM * SDIM];

__global__ __launch_bounds__(256) void precompute_C_kernel(
    const float* __restrict__ adj, const float* __restrict__ dist,
    const float* __restrict__ mask)
{
    int row = blockIdx.x;
    int b = row >> 9;
    const float* arow = adj  + (size_t)row * SDIM;
    const float* drow = dist + (size_t)row * SDIM;
    const float* mrow = mask + (size_t)b * SDIM;
    float* crow = g_C + (size_t)row * SDIM;
    int tid = threadIdx.x, w = tid >> 5, l = tid & 31;

    float a0 = arow[tid], a1 = arow[tid + 256];
    float d0 = drow[tid], d1 = drow[tid + 256];
    float m0 = mrow[tid], m1 = mrow[tid + 256];
    float x0 = (m0 == 0.0f) ? -CUDART_INF_F : -d0;
    float x1 = (m1 == 0.0f) ? -CUDART_INF_F : -d1;

    float asum = a0 + a1, xmax = fmaxf(x0, x1);
    #pragma unroll
    for (int o = 16; o > 0; o >>= 1) {
        asum += __shfl_xor_sync(0xffffffffu, asum, o);
        xmax = fmaxf(xmax, __shfl_xor_sync(0xffffffffu, xmax, o));
    }
    __shared__ float rs[8], rm[8], re[8];
    if (l == 0) { rs[w] = asum; rm[w] = xmax; }
    __syncthreads();
    float ts = 0.0f, tm = -CUDART_INF_F;
    #pragma unroll
    for (int i = 0; i < 8; i++) { ts += rs[i]; tm = fmaxf(tm, rm[i]); }

    float e0 = __expf(x0 - tm), e1 = __expf(x1 - tm), es = e0 + e1;
    #pragma unroll
    for (int o = 16; o > 0; o >>= 1) es += __shfl_xor_sync(0xffffffffu, es, o);
    if (l == 0) re[w] = es;
    __syncthreads();
    float te = 0.0f;
    #pragma unroll
    for (int i = 0; i < 8; i++) te += re[i];

    float inv_a = 1.0f / (ts + 1e-6f), inv_e = 1.0f / te;
    crow[tid]       = L_DIST * e0 * inv_e + L_ADJ * a0 * inv_a;
    crow[tid + 256] = L_DIST * e1 * inv_e + L_ADJ * a1 * inv_a;
}

__device__ __forceinline__ void mma_bf16(float* c, const uint32_t* a, const uint32_t* b) {
    asm volatile("mma.sync.aligned.m16n8k16.row.col.f32.bf16.bf16.f32 "
        "{%0,%1,%2,%3}, {%4,%5,%6,%7}, {%8,%9}, {%0,%1,%2,%3};"
        : "+f"(c[0]), "+f"(c[1]), "+f"(c[2]), "+f"(c[3])
        : "r"(a[0]), "r"(a[1]), "r"(a[2]), "r"(a[3]), "r"(b[0]), "r"(b[1]));
}
__device__ __forceinline__ void ldm_x4(uint32_t* r, uint32_t a) {
    asm volatile("ldmatrix.sync.aligned.m8n8.x4.shared.b16 {%0,%1,%2,%3}, [%4];"
        : "=r"(r[0]), "=r"(r[1]), "=r"(r[2]), "=r"(r[3]) : "r"(a));
}
__device__ __forceinline__ void ldm_x4t(uint32_t* r, uint32_t a) {
    asm volatile("ldmatrix.sync.aligned.m8n8.x4.trans.shared.b16 {%0,%1,%2,%3}, [%4];"
        : "=r"(r[0]), "=r"(r[1]), "=r"(r[2]), "=r"(r[3]) : "r"(a));
}
__device__ __forceinline__ uint32_t smem_u32(const void* p) {
    uint32_t a;
    asm("{ .reg .u64 t; cvta.to.shared.u64 t, %1; cvt.u32.u64 %0, t; }" : "=r"(a) : "l"(p));
    return a;
}
__device__ __forceinline__ uint32_t packbf(float lo, float hi) {
    uint32_t r;
    asm("cvt.rn.bf16x2.f32 %0, %1, %2;" : "=r"(r) : "f"(hi), "f"(lo));
    return r;
}
__device__ __forceinline__ float bfround(float x) {
    return __bfloat162float(__float2bfloat16_rn(x));
}

__global__ __launch_bounds__(512) void attn_mma_kernel(
    const float* __restrict__ Q, const float* __restrict__ K,
    const float* __restrict__ V, const float* __restrict__ mask,
    float* __restrict__ Og, float* __restrict__ Pg)
{
    extern __shared__ char smem[];
    uint32_t sb = smem_u32(smem);
    float* sMask = (float*)(smem + OFF_MASK);

    int tid = threadIdx.x;
    int wid = tid >> 5, l = tid & 31;
    int lr = l >> 2, lc = l & 3;
    int lr8 = l & 7, lg = (l >> 3) & 1, kg4 = l >> 4;
    int wm = wid >> 2, wn = wid & 3;   // m4 x n4

    int qt = blockIdx.x, h = blockIdx.y, b = blockIdx.z;
    int q0 = qt * QT;
    size_t bh_ = (size_t)b * HH + h;
    const float* Qp = Q + (bh_ * SDIM + q0) * DDIM;
    const float* Kp = K + bh_ * SDIM * DDIM;
    const float* Vp = V + bh_ * SDIM * DDIM;
    const float* Mp = mask + (size_t)b * SDIM;
    const float* Cp = g_C + ((size_t)b * SDIM + q0) * SDIM;
    float* Op = Og + (bh_ * SDIM + q0) * DDIM;
    float* Pp = Pg + (bh_ * SDIM + q0) * SDIM;

    sMask[tid] = Mp[tid];

    // ---- Q (x 1/8) -> hi/lo bf16 smem ----
    {
        const float4* Q4 = (const float4*)Qp;
        #pragma unroll
        for (int t = 0; t < 2; ++t) {
            int idx = tid + 512 * t;
            float4 f = Q4[idx];
            int r = idx >> 4, c = (idx & 15) << 2;
            float v0 = f.x * 0.125f, v1 = f.y * 0.125f, v2 = f.z * 0.125f, v3 = f.w * 0.125f;
            char* dst = smem + OFF_QS + r * KSTRB + 2 * c;
            *(uint2*)dst = make_uint2(packbf(v0, v1), packbf(v2, v3));
            *(uint2*)(dst + 9216) = make_uint2(
                packbf(v0 - bfround(v0), v1 - bfround(v1)),
                packbf(v2 - bfround(v2), v3 - bfround(v3)));
        }
    }
    // ---- K tile 0 -> buf0; prefetch tile 1 ----
    {
        const float4* K4 = (const float4*)Kp;
        #pragma unroll
        for (int t = 0; t < 2; ++t) {
            int idx = tid + 512 * t;
            float4 f = K4[idx];
            int r = idx >> 4, c = (idx & 15) << 2;
            char* dst = smem + OFF_K + r * KSTRB + 2 * c;
            *(uint2*)dst = make_uint2(packbf(f.x, f.y), packbf(f.z, f.w));
            *(uint2*)(dst + 9216) = make_uint2(
                packbf(f.x - bfround(f.x), f.y - bfround(f.y)),
                packbf(f.z - bfround(f.z), f.w - bfround(f.w)));
        }
    }
    float4 pf[2];
    {
        const float4* K4 = (const float4*)(Kp + 4096);
        pf[0] = K4[tid]; pf[1] = K4[tid + 512];
    }
    __syncthreads();

    // ---- resident Q fragments ----
    uint32_t qah[4][4], qal[4][4];
    {
        uint32_t ra = sb + OFF_QS + (16 * wm + lr8 + 8 * lg) * KSTRB + 16 * kg4;
        #pragma unroll
        for (int ks = 0; ks < 4; ++ks) {
            ldm_x4(qah[ks], ra + ks * 32);
            ldm_x4(qal[ks], ra + 9216 + ks * 32);
        }
    }

    // ---- Phase 1: scores (regs), double-buffered K, pipelined B-frags ----
    float sc[8][2][4];
    #pragma unroll
    for (int kt = 0; kt < 8; ++kt) {
        #pragma unroll
        for (int nf = 0; nf < 2; ++nf)
            #pragma unroll
            for (int e = 0; e < 4; ++e) sc[kt][nf][e] = 0.0f;

        uint32_t rbase = sb + OFF_K + (kt & 1) * 18432
                         + (16 * wn + lr8 + 8 * kg4) * KSTRB + 16 * lg;
        uint32_t bh[2][4];
        ldm_x4(bh[0], rbase);
        #pragma unroll
        for (int ks = 0; ks < 4; ++ks) {
            int cc = ks & 1;
            if (ks < 3) ldm_x4(bh[cc ^ 1], rbase + 32 * (ks + 1));
            uint32_t bl[4];
            ldm_x4(bl, rbase + 9216 + 32 * ks);
            #pragma unroll
            for (int nf = 0; nf < 2; ++nf) {
                mma_bf16(sc[kt][nf], qah[ks], bh[cc] + 2 * nf);
                mma_bf16(sc[kt][nf], qal[ks], bh[cc] + 2 * nf);
                mma_bf16(sc[kt][nf], qah[ks], bl + 2 * nf);
            }
        }
        if (kt < 7) {
            #pragma unroll
            for (int t = 0; t < 2; ++t) {
                int idx = tid + 512 * t;
                float4 f = pf[t];
                int r = idx >> 4, c = (idx & 15) << 2;
                char* dst = smem + OFF_K + ((kt + 1) & 1) * 18432 + r * KSTRB + 2 * c;
                *(uint2*)dst = make_uint2(packbf(f.x, f.y), packbf(f.z, f.w));
                *(uint2*)(dst + 9216) = make_uint2(
                    packbf(f.x - bfround(f.x), f.y - bfround(f.y)),
                    packbf(f.z - bfround(f.z), f.w - bfround(f.w)));
            }
            __syncthreads();
            if (kt < 6) {
                const float4* K4 = (const float4*)(Kp + (size_t)(kt + 2) * 4096);
                pf[0] = K4[tid]; pf[1] = K4[tid + 512];
            }
        }
    }

    // ---- V chunk 0 LDG (64 keys x 64 dims; latency hidden by softmax math) ----
    const float4* V4 = (const float4*)Vp;
    float4 vf[2];
    vf[0] = V4[tid]; vf[1] = V4[tid + 512];

    // ---- softmax: mask + row max ----
    int r0 = 16 * wm + lr, r1 = r0 + 8;
    {
        float2 mk;
        #pragma unroll
        for (int j = 0; j < 8; ++j)
            #pragma unroll
            for (int nf = 0; nf < 2; ++nf) {
                mk = *(float2*)(smem + OFF_MASK + 4 * (64 * j + 16 * wn + 8 * nf + 2 * lc));
                if (mk.x == 0.0f) { sc[j][nf][0] = -1e12f; sc[j][nf][2] = -1e12f; }
                if (mk.y == 0.0f) { sc[j][nf][1] = -1e12f; sc[j][nf][3] = -1e12f; }
            }
    }
    float mx0 = -CUDART_INF_F, mx1 = -CUDART_INF_F;
    #pragma unroll
    for (int j = 0; j < 8; ++j)
        #pragma unroll
        for (int nf = 0; nf < 2; ++nf) {
            mx0 = fmaxf(mx0, fmaxf(sc[j][nf][0], sc[j][nf][1]));
            mx1 = fmaxf(mx1, fmaxf(sc[j][nf][2], sc[j][nf][3]));
        }
    #pragma unroll
    for (int o = 1; o < 4; o <<= 1) {
        mx0 = fmaxf(mx0, __shfl_xor_sync(0xffffffffu, mx0, o));
        mx1 = fmaxf(mx1, __shfl_xor_sync(0xffffffffu, mx1, o));
    }
    if (lc == 0) {
        ((float*)(smem + OFF_RM))[r0 * 4 + wn] = mx0;
        ((float*)(smem + OFF_RM))[r1 * 4 + wn] = mx1;
    }
    // STS V chunk 0 -> buf0 (dead since kt6->7 barrier); RM barrier covers it
    #pragma unroll
    for (int t = 0; t < 2; ++t) {
        int idx = tid + 512 * t;
        float4 f = vf[t];
        int r = idx >> 4, c = (idx & 15) << 2;
        char* dst = smem + OFF_K + r * KSTRB + 2 * c;
        *(uint2*)dst = make_uint2(packbf(f.x, f.y), packbf(f.z, f.w));
        *(uint2*)(dst + 9216) = make_uint2(
            packbf(f.x - bfround(f.x), f.y - bfround(f.y)),
            packbf(f.z - bfround(f.z), f.w - bfround(f.w)));
    }
    __syncthreads();
    {
        float4 m0 = *(float4*)(smem + OFF_RM + r0 * 16);
        float4 m1 = *(float4*)(smem + OFF_RM + r1 * 16);
        mx0 = fmaxf(fmaxf(m0.x, m0.y), fmaxf(m0.z, m0.w));
        mx1 = fmaxf(fmaxf(m1.x, m1.y), fmaxf(m1.z, m1.w));
    }
    // LDG V chunk 1 (hidden under exp/sum math)
    vf[0] = V4[1024 + tid]; vf[1] = V4[1024 + tid + 512];

    float s0 = 0.0f, s1 = 0.0f;
    #pragma unroll
    for (int j = 0; j < 8; ++j)
        #pragma unroll
        for (int nf = 0; nf < 2; ++nf) {
            sc[j][nf][0] = __expf(sc[j][nf][0] - mx0);
            sc[j][nf][1] = __expf(sc[j][nf][1] - mx0);
            sc[j][nf][2] = __expf(sc[j][nf][2] - mx1);
            sc[j][nf][3] = __expf(sc[j][nf][3] - mx1);
            s0 += sc[j][nf][0] + sc[j][nf][1];
            s1 += sc[j][nf][2] + sc[j][nf][3];
        }
    #pragma unroll
    for (int o = 1; o < 4; o <<= 1) {
        s0 += __shfl_xor_sync(0xffffffffu, s0, o);
        s1 += __shfl_xor_sync(0xffffffffu, s1, o);
    }
    if (lc == 0) {
        ((float*)(smem + OFF_RS))[r0 * 4 + wn] = s0;
        ((float*)(smem + OFF_RS))[r1 * 4 + wn] = s1;
    }
    // first C chunk prefetch while the sum barrier drains
    int colb = 16 * wn + 2 * lc;
    float2 cb[2][2][2];
    #pragma unroll
    for (int nf = 0; nf < 2; ++nf) {
        cb[0][0][nf] = __ldg((const float2*)(Cp + (size_t)r0 * SDIM + colb + 8 * nf));
        cb[0][1][nf] = __ldg((const float2*)(Cp + (size_t)r1 * SDIM + colb + 8 * nf));
    }
    __syncthreads();
    float inv0, inv1;
    {
        float4 t0 = *(float4*)(smem + OFF_RS + r0 * 16);
        float4 t1 = *(float4*)(smem + OFF_RS + r1 * 16);
        inv0 = 1.0f / (t0.x + t0.y + t0.z + t0.w);
        inv1 = 1.0f / (t1.x + t1.y + t1.z + t1.w);
    }

    // ---- fused phase 2+3 per 64-key chunk j; V streamed through K buffers ----
    float accO[8][4];
    #pragma unroll
    for (int nj = 0; nj < 8; ++nj)
        #pragma unroll
        for (int e = 0; e < 4; ++e) accO[nj][e] = 0.0f;

    #pragma unroll
    for (int j = 0; j < 8; ++j) {
        int cur = j & 1, nxt = cur ^ 1;
        if (j < 7) {
            int coln = 64 * (j + 1) + colb;
            #pragma unroll
            for (int nf = 0; nf < 2; ++nf) {
                cb[nxt][0][nf] = __ldg((const float2*)(Cp + (size_t)r0 * SDIM + coln + 8 * nf));
                cb[nxt][1][nf] = __ldg((const float2*)(Cp + (size_t)r1 * SDIM + coln + 8 * nf));
            }
        }
        uint32_t wah[4], wal[4];
        #pragma unroll
        for (int nf = 0; nf < 2; ++nf) {
            int col = 64 * j + colb + 8 * nf;
            float p00 = sc[j][nf][0] * inv0, p01 = sc[j][nf][1] * inv0;
            float p10 = sc[j][nf][2] * inv1, p11 = sc[j][nf][3] * inv1;
            __stcs((float2*)(Pp + (size_t)r0 * SDIM + col), make_float2(p00, p01));
            __stcs((float2*)(Pp + (size_t)r1 * SDIM + col), make_float2(p10, p11));
            float w00 = fmaf(L_ATT, p00, cb[cur][0][nf].x);
            float w01 = fmaf(L_ATT, p01, cb[cur][0][nf].y);
            float w10 = fmaf(L_ATT, p10, cb[cur][1][nf].x);
            float w11 = fmaf(L_ATT, p11, cb[cur][1][nf].y);
            wah[2 * nf]     = packbf(w00, w01);
            wah[2 * nf + 1] = packbf(w10, w11);
            wal[2 * nf]     = packbf(w00 - bfround(w00), w01 - bfround(w01));
            wal[2 * nf + 1] = packbf(w10 - bfround(w10), w11 - bfround(w11));
        }

        uint32_t vrow = sb + OFF_K + cur * 18432
                        + (16 * wn + lr8 + 8 * lg) * KSTRB + 9216 * kg4;
        uint32_t vb[2][4];
        ldm_x4t(vb[0], vrow);
        #pragma unroll
        for (int nj = 0; nj < 8; ++nj) {
            int vc = nj & 1;
            if (nj < 7) ldm_x4t(vb[vc ^ 1], vrow + 16 * (nj + 1));
            mma_bf16(accO[nj], wah, vb[vc]);
            mma_bf16(accO[nj], wal, vb[vc]);
            mma_bf16(accO[nj], wah, vb[vc] + 2);
        }

        if (j < 7) {
            // STS V chunk j+1 -> other buf (its readers finished at end of j-1)
            #pragma unroll
            for (int t = 0; t < 2; ++t) {
                int idx = tid + 512 * t;
                float4 f = vf[t];
                int r = idx >> 4, c = (idx & 15) << 2;
                char* dst = smem + OFF_K + nxt * 18432 + r * KSTRB + 2 * c;
                *(uint2*)dst = make_uint2(packbf(f.x, f.y), packbf(f.z, f.w));
                *(uint2*)(dst + 9216) = make_uint2(
                    packbf(f.x - bfround(f.x), f.y - bfround(f.y)),
                    packbf(f.z - bfround(f.z), f.w - bfround(f.w)));
            }
            __syncthreads();
            if (j < 6) {
                vf[0] = V4[(size_t)(j + 2) * 1024 + tid];
                vf[1] = V4[(size_t)(j + 2) * 1024 + tid + 512];
            }
        }
    }

    // ---- parallel reduction: 4 disjoint regions, one barrier ----
    __syncthreads();
    {
        static const int REDB[4] = {REDB0, REDB1, REDB2, REDB3};
        char* reg_ = smem + REDB[wn];
        #pragma unroll
        for (int nj = 0; nj < 8; ++nj) {
            int col = 8 * nj + 2 * lc;
            *(float2*)(reg_ + (r0 * RSTR + col) * 4) = make_float2(accO[nj][0], accO[nj][1]);
            *(float2*)(reg_ + (r1 * RSTR + col) * 4) = make_float2(accO[nj][2], accO[nj][3]);
        }
    }
    __syncthreads();

    #pragma unroll
    for (int t = 0; t < 2; ++t) {
        int idx = tid + 512 * t;
        int row = idx >> 4, c0 = (idx & 15) << 2;
        float4 a0 = *(float4*)(smem + REDB0 + (row * RSTR + c0) * 4);
        float4 a1 = *(float4*)(smem + REDB1 + (row * RSTR + c0) * 4);
        float4 a2 = *(float4*)(smem + REDB2 + (row * RSTR + c0) * 4);
        float4 a3 = *(float4*)(smem + REDB3 + (row * RSTR + c0) * 4);
        float4 o;
        o.x = (a0.x + a1.x) + (a2.x + a3.x);
        o.y = (a0.y + a1.y) + (a2.y + a3.y);
        o.z = (a0.z + a1.z) + (a2.z + a3.z);
        o.w = (a0.w + a1.w) + (a2.w + a3.w);
        *(float4*)(Op + row * DDIM + c0) = o;
    }
}

extern "C" void kernel_launch(void* const* d_in, const int* in_sizes, int n_in,
                              void* d_out, int out_size)
{
    const float* Q    = (const float*)d_in[0];
    const float* K    = (const float*)d_in[1];
    const float* V    = (const float*)d_in[2];
    const float* mask = (const float*)d_in[3];
    const float* adj  = (const float*)d_in[4];
    const float* dist = (const float*)d_in[5];

    float* outp  = (float*)d_out;
    float* pattn = outp + (size_t)BB * HH * SDIM * DDIM;

    precompute_C_kernel<<<BB * SDIM, 256>>>(adj, dist, mask);

    cudaFuncSetAttribute(attn_mma_kernel,
                         cudaFuncAttributeMaxDynamicSharedMemorySize, SMEM_BYTES);
    dim3 grid(SDIM / QT, HH, BB);
    attn_mma_kernel<<<grid, THREADS, SMEM_BYTES>>>(Q, K, V, mask, outp, pattn);
}

// round 14
// speedup vs baseline: 1.2744x; 1.2213x over previous
#include <cuda_runtime.h>
#include <cuda_fp16.h>
#include <math_constants.h>
#include <cstdint>

#define BB 16
#define HH 16
#define SDIM 512
#define DDIM 64
#define QT 64
#define THREADS 512
#define KSTRB 144

#define L_ATT 0.33f
#define L_DIST 0.33f
#define L_ADJ (1.0f - 0.33f - 0.33f)

// ---- smem map (bytes) ----
#define OFF_QS   0          // Q hi 64x144 fp16 (9216), lo at +9216
#define OFF_K    18432      // 2 bufs x 9216 (hi only); V chunks stream here in phase 3
#define RSTR     68
#define REDB0    0          // Q region (dead after frag loads)
#define REDB1    18432      // K bufs
#define REDB2    36864      // dedicated
#define REDB3    54272      // dedicated
#define OFF_RM   71680
#define OFF_RS   72704
#define OFF_MASK 73728
#define SMEM_BYTES 75776

__device__ float g_C[(size_t)BB * SDIM * SDIM];

__global__ __launch_bounds__(256) void precompute_C_kernel(
    const float* __restrict__ adj, const float* __restrict__ dist,
    const float* __restrict__ mask)
{
    int row = blockIdx.x;
    int b = row >> 9;
    const float* arow = adj  + (size_t)row * SDIM;
    const float* drow = dist + (size_t)row * SDIM;
    const float* mrow = mask + (size_t)b * SDIM;
    float* crow = g_C + (size_t)row * SDIM;
    int tid = threadIdx.x, w = tid >> 5, l = tid & 31;

    float a0 = arow[tid], a1 = arow[tid + 256];
    float d0 = drow[tid], d1 = drow[tid + 256];
    float m0 = mrow[tid], m1 = mrow[tid + 256];
    float x0 = (m0 == 0.0f) ? -CUDART_INF_F : -d0;
    float x1 = (m1 == 0.0f) ? -CUDART_INF_F : -d1;

    float asum = a0 + a1, xmax = fmaxf(x0, x1);
    #pragma unroll
    for (int o = 16; o > 0; o >>= 1) {
        asum += __shfl_xor_sync(0xffffffffu, asum, o);
        xmax = fmaxf(xmax, __shfl_xor_sync(0xffffffffu, xmax, o));
    }
    __shared__ float rs[8], rm[8], re[8];
    if (l == 0) { rs[w] = asum; rm[w] = xmax; }
    __syncthreads();
    float ts = 0.0f, tm = -CUDART_INF_F;
    #pragma unroll
    for (int i = 0; i < 8; i++) { ts += rs[i]; tm = fmaxf(tm, rm[i]); }

    float e0 = __expf(x0 - tm), e1 = __expf(x1 - tm), es = e0 + e1;
    #pragma unroll
    for (int o = 16; o > 0; o >>= 1) es += __shfl_xor_sync(0xffffffffu, es, o);
    if (l == 0) re[w] = es;
    __syncthreads();
    float te = 0.0f;
    #pragma unroll
    for (int i = 0; i < 8; i++) te += re[i];

    float inv_a = 1.0f / (ts + 1e-6f), inv_e = 1.0f / te;
    crow[tid]       = L_DIST * e0 * inv_e + L_ADJ * a0 * inv_a;
    crow[tid + 256] = L_DIST * e1 * inv_e + L_ADJ * a1 * inv_a;
}

__device__ __forceinline__ void mma_f16(float* c, const uint32_t* a, const uint32_t* b) {
    asm volatile("mma.sync.aligned.m16n8k16.row.col.f32.f16.f16.f32 "
        "{%0,%1,%2,%3}, {%4,%5,%6,%7}, {%8,%9}, {%0,%1,%2,%3};"
        : "+f"(c[0]), "+f"(c[1]), "+f"(c[2]), "+f"(c[3])
        : "r"(a[0]), "r"(a[1]), "r"(a[2]), "r"(a[3]), "r"(b[0]), "r"(b[1]));
}
__device__ __forceinline__ void ldm_x4(uint32_t* r, uint32_t a) {
    asm volatile("ldmatrix.sync.aligned.m8n8.x4.shared.b16 {%0,%1,%2,%3}, [%4];"
        : "=r"(r[0]), "=r"(r[1]), "=r"(r[2]), "=r"(r[3]) : "r"(a));
}
__device__ __forceinline__ void ldm_x4t(uint32_t* r, uint32_t a) {
    asm volatile("ldmatrix.sync.aligned.m8n8.x4.trans.shared.b16 {%0,%1,%2,%3}, [%4];"
        : "=r"(r[0]), "=r"(r[1]), "=r"(r[2]), "=r"(r[3]) : "r"(a));
}
__device__ __forceinline__ uint32_t smem_u32(const void* p) {
    uint32_t a;
    asm("{ .reg .u64 t; cvta.to.shared.u64 t, %1; cvt.u32.u64 %0, t; }" : "=r"(a) : "l"(p));
    return a;
}
// pack two f32 -> f16x2 (first arg in low half)
__device__ __forceinline__ uint32_t packhf(float lo, float hi) {
    uint32_t r;
    asm("cvt.rn.f16x2.f32 %0, %1, %2;" : "=r"(r) : "f"(hi), "f"(lo));
    return r;
}
__device__ __forceinline__ float hround(float x) {
    return __half2float(__float2half_rn(x));
}

__global__ __launch_bounds__(512) void attn_mma_kernel(
    const float* __restrict__ Q, const float* __restrict__ K,
    const float* __restrict__ V, const float* __restrict__ mask,
    float* __restrict__ Og, float* __restrict__ Pg)
{
    extern __shared__ char smem[];
    uint32_t sb = smem_u32(smem);
    float* sMask = (float*)(smem + OFF_MASK);

    int tid = threadIdx.x;
    int wid = tid >> 5, l = tid & 31;
    int lr = l >> 2, lc = l & 3;
    int lr8 = l & 7, lg = (l >> 3) & 1, kg4 = l >> 4;
    int wm = wid >> 2, wn = wid & 3;   // m4 x n4

    int qt = blockIdx.x, h = blockIdx.y, b = blockIdx.z;
    int q0 = qt * QT;
    size_t bh_ = (size_t)b * HH + h;
    const float* Qp = Q + (bh_ * SDIM + q0) * DDIM;
    const float* Kp = K + bh_ * SDIM * DDIM;
    const float* Vp = V + bh_ * SDIM * DDIM;
    const float* Mp = mask + (size_t)b * SDIM;
    const float* Cp = g_C + ((size_t)b * SDIM + q0) * SDIM;
    float* Op = Og + (bh_ * SDIM + q0) * DDIM;
    float* Pp = Pg + (bh_ * SDIM + q0) * SDIM;

    sMask[tid] = Mp[tid];

    // ---- Q (x 1/8) -> fp16 hi/lo smem ----
    {
        const float4* Q4 = (const float4*)Qp;
        #pragma unroll
        for (int t = 0; t < 2; ++t) {
            int idx = tid + 512 * t;
            float4 f = Q4[idx];
            int r = idx >> 4, c = (idx & 15) << 2;
            float v0 = f.x * 0.125f, v1 = f.y * 0.125f, v2 = f.z * 0.125f, v3 = f.w * 0.125f;
            char* dst = smem + OFF_QS + r * KSTRB + 2 * c;
            *(uint2*)dst = make_uint2(packhf(v0, v1), packhf(v2, v3));
            *(uint2*)(dst + 9216) = make_uint2(
                packhf(v0 - hround(v0), v1 - hround(v1)),
                packhf(v2 - hround(v2), v3 - hround(v3)));
        }
    }
    // ---- K tile 0 -> buf0 (hi only); prefetch tile 1 ----
    {
        const float4* K4 = (const float4*)Kp;
        #pragma unroll
        for (int t = 0; t < 2; ++t) {
            int idx = tid + 512 * t;
            float4 f = K4[idx];
            int r = idx >> 4, c = (idx & 15) << 2;
            *(uint2*)(smem + OFF_K + r * KSTRB + 2 * c) =
                make_uint2(packhf(f.x, f.y), packhf(f.z, f.w));
        }
    }
    float4 pf[2];
    {
        const float4* K4 = (const float4*)(Kp + 4096);
        pf[0] = K4[tid]; pf[1] = K4[tid + 512];
    }
    __syncthreads();

    // ---- resident Q fragments (hi + lo) ----
    uint32_t qah[4][4], qal[4][4];
    {
        uint32_t ra = sb + OFF_QS + (16 * wm + lr8 + 8 * lg) * KSTRB + 16 * kg4;
        #pragma unroll
        for (int ks = 0; ks < 4; ++ks) {
            ldm_x4(qah[ks], ra + ks * 32);
            ldm_x4(qal[ks], ra + 9216 + ks * 32);
        }
    }

    // ---- Phase 1: scores (regs), double-buffered K (hi only), 2-pass fp16 ----
    float sc[8][2][4];
    #pragma unroll
    for (int kt = 0; kt < 8; ++kt) {
        #pragma unroll
        for (int nf = 0; nf < 2; ++nf)
            #pragma unroll
            for (int e = 0; e < 4; ++e) sc[kt][nf][e] = 0.0f;

        uint32_t rbase = sb + OFF_K + (kt & 1) * 9216
                         + (16 * wn + lr8 + 8 * kg4) * KSTRB + 16 * lg;
        uint32_t bh[2][4];
        ldm_x4(bh[0], rbase);
        #pragma unroll
        for (int ks = 0; ks < 4; ++ks) {
            int cc = ks & 1;
            if (ks < 3) ldm_x4(bh[cc ^ 1], rbase + 32 * (ks + 1));
            #pragma unroll
            for (int nf = 0; nf < 2; ++nf) {
                mma_f16(sc[kt][nf], qah[ks], bh[cc] + 2 * nf);
                mma_f16(sc[kt][nf], qal[ks], bh[cc] + 2 * nf);
            }
        }
        if (kt < 7) {
            #pragma unroll
            for (int t = 0; t < 2; ++t) {
                int idx = tid + 512 * t;
                float4 f = pf[t];
                int r = idx >> 4, c = (idx & 15) << 2;
                *(uint2*)(smem + OFF_K + ((kt + 1) & 1) * 9216 + r * KSTRB + 2 * c) =
                    make_uint2(packhf(f.x, f.y), packhf(f.z, f.w));
            }
            __syncthreads();
            if (kt < 6) {
                const float4* K4 = (const float4*)(Kp + (size_t)(kt + 2) * 4096);
                pf[0] = K4[tid]; pf[1] = K4[tid + 512];
            }
        }
    }

    // ---- V chunk 0 LDG (latency hidden by softmax math) ----
    const float4* V4 = (const float4*)Vp;
    float4 vf[2];
    vf[0] = V4[tid]; vf[1] = V4[tid + 512];

    // ---- softmax: mask + row max ----
    int r0 = 16 * wm + lr, r1 = r0 + 8;
    {
        float2 mk;
        #pragma unroll
        for (int j = 0; j < 8; ++j)
            #pragma unroll
            for (int nf = 0; nf < 2; ++nf) {
                mk = *(float2*)(smem + OFF_MASK + 4 * (64 * j + 16 * wn + 8 * nf + 2 * lc));
                if (mk.x == 0.0f) { sc[j][nf][0] = -1e12f; sc[j][nf][2] = -1e12f; }
                if (mk.y == 0.0f) { sc[j][nf][1] = -1e12f; sc[j][nf][3] = -1e12f; }
            }
    }
    float mx0 = -CUDART_INF_F, mx1 = -CUDART_INF_F;
    #pragma unroll
    for (int j = 0; j < 8; ++j)
        #pragma unroll
        for (int nf = 0; nf < 2; ++nf) {
            mx0 = fmaxf(mx0, fmaxf(sc[j][nf][0], sc[j][nf][1]));
            mx1 = fmaxf(mx1, fmaxf(sc[j][nf][2], sc[j][nf][3]));
        }
    #pragma unroll
    for (int o = 1; o < 4; o <<= 1) {
        mx0 = fmaxf(mx0, __shfl_xor_sync(0xffffffffu, mx0, o));
        mx1 = fmaxf(mx1, __shfl_xor_sync(0xffffffffu, mx1, o));
    }
    if (lc == 0) {
        ((float*)(smem + OFF_RM))[r0 * 4 + wn] = mx0;
        ((float*)(smem + OFF_RM))[r1 * 4 + wn] = mx1;
    }
    // STS V chunk 0 -> buf0 (dead since kt6->7 barrier); RM barrier covers it
    #pragma unroll
    for (int t = 0; t < 2; ++t) {
        int idx = tid + 512 * t;
        float4 f = vf[t];
        int r = idx >> 4, c = (idx & 15) << 2;
        *(uint2*)(smem + OFF_K + r * KSTRB + 2 * c) =
            make_uint2(packhf(f.x, f.y), packhf(f.z, f.w));
    }
    __syncthreads();
    {
        float4 m0 = *(float4*)(smem + OFF_RM + r0 * 16);
        float4 m1 = *(float4*)(smem + OFF_RM + r1 * 16);
        mx0 = fmaxf(fmaxf(m0.x, m0.y), fmaxf(m0.z, m0.w));
        mx1 = fmaxf(fmaxf(m1.x, m1.y), fmaxf(m1.z, m1.w));
    }
    // LDG V chunk 1 (hidden under exp/sum math)
    vf[0] = V4[1024 + tid]; vf[1] = V4[1024 + tid + 512];

    float s0 = 0.0f, s1 = 0.0f;
    #pragma unroll
    for (int j = 0; j < 8; ++j)
        #pragma unroll
        for (int nf = 0; nf < 2; ++nf) {
            sc[j][nf][0] = __expf(sc[j][nf][0] - mx0);
            sc[j][nf][1] = __expf(sc[j][nf][1] - mx0);
            sc[j][nf][2] = __expf(sc[j][nf][2] - mx1);
            sc[j][nf][3] = __expf(sc[j][nf][3] - mx1);
            s0 += sc[j][nf][0] + sc[j][nf][1];
            s1 += sc[j][nf][2] + sc[j][nf][3];
        }
    #pragma unroll
    for (int o = 1; o < 4; o <<= 1) {
        s0 += __shfl_xor_sync(0xffffffffu, s0, o);
        s1 += __shfl_xor_sync(0xffffffffu, s1, o);
    }
    if (lc == 0) {
        ((float*)(smem + OFF_RS))[r0 * 4 + wn] = s0;
        ((float*)(smem + OFF_RS))[r1 * 4 + wn] = s1;
    }
    // first C chunk prefetch while the sum barrier drains
    int colb = 16 * wn + 2 * lc;
    float2 cb[2][2][2];
    #pragma unroll
    for (int nf = 0; nf < 2; ++nf) {
        cb[0][0][nf] = __ldg((const float2*)(Cp + (size_t)r0 * SDIM + colb + 8 * nf));
        cb[0][1][nf] = __ldg((const float2*)(Cp + (size_t)r1 * SDIM + colb + 8 * nf));
    }
    __syncthreads();
    float inv0, inv1;
    {
        float4 t0 = *(float4*)(smem + OFF_RS + r0 * 16);
        float4 t1 = *(float4*)(smem + OFF_RS + r1 * 16);
        inv0 = 1.0f / (t0.x + t0.y + t0.z + t0.w);
        inv1 = 1.0f / (t1.x + t1.y + t1.z + t1.w);
    }

    // ---- fused phase 2+3 per 64-key chunk j; V (hi only) streamed through K bufs ----
    float accO[8][4];
    #pragma unroll
    for (int nj = 0; nj < 8; ++nj)
        #pragma unroll
        for (int e = 0; e < 4; ++e) accO[nj][e] = 0.0f;

    #pragma unroll
    for (int j = 0; j < 8; ++j) {
        int cur = j & 1, nxt = cur ^ 1;
        if (j < 7) {
            int coln = 64 * (j + 1) + colb;
            #pragma unroll
            for (int nf = 0; nf < 2; ++nf) {
                cb[nxt][0][nf] = __ldg((const float2*)(Cp + (size_t)r0 * SDIM + coln + 8 * nf));
                cb[nxt][1][nf] = __ldg((const float2*)(Cp + (size_t)r1 * SDIM + coln + 8 * nf));
            }
        }
        uint32_t wah[4], wal[4];
        #pragma unroll
        for (int nf = 0; nf < 2; ++nf) {
            int col = 64 * j + colb + 8 * nf;
            float p00 = sc[j][nf][0] * inv0, p01 = sc[j][nf][1] * inv0;
            float p10 = sc[j][nf][2] * inv1, p11 = sc[j][nf][3] * inv1;
            __stcs((float2*)(Pp + (size_t)r0 * SDIM + col), make_float2(p00, p01));
            __stcs((float2*)(Pp + (size_t)r1 * SDIM + col), make_float2(p10, p11));
            float w00 = fmaf(L_ATT, p00, cb[cur][0][nf].x);
            float w01 = fmaf(L_ATT, p01, cb[cur][0][nf].y);
            float w10 = fmaf(L_ATT, p10, cb[cur][1][nf].x);
            float w11 = fmaf(L_ATT, p11, cb[cur][1][nf].y);
            wah[2 * nf]     = packhf(w00, w01);
            wah[2 * nf + 1] = packhf(w10, w11);
            wal[2 * nf]     = packhf(w00 - hround(w00), w01 - hround(w01));
            wal[2 * nf + 1] = packhf(w10 - hround(w10), w11 - hround(w11));
        }

        // V b-frags: 2 n-tiles per ldm.x4t (kg4 selects the pair member)
        uint32_t vbase = sb + OFF_K + cur * 9216
                         + (16 * wn + lr8 + 8 * lg) * KSTRB + 16 * kg4;
        uint32_t vb[2][4];
        ldm_x4t(vb[0], vbase);
        #pragma unroll
        for (int njp = 0; njp < 4; ++njp) {
            int vc = njp & 1;
            if (njp < 3) ldm_x4t(vb[vc ^ 1], vbase + 32 * (njp + 1));
            mma_f16(accO[2 * njp],     wah, vb[vc]);
            mma_f16(accO[2 * njp],     wal, vb[vc]);
            mma_f16(accO[2 * njp + 1], wah, vb[vc] + 2);
            mma_f16(accO[2 * njp + 1], wal, vb[vc] + 2);
        }

        if (j < 7) {
            // STS V chunk j+1 -> other buf (its readers finished at end of j-1)
            #pragma unroll
            for (int t = 0; t < 2; ++t) {
                int idx = tid + 512 * t;
                float4 f = vf[t];
                int r = idx >> 4, c = (idx & 15) << 2;
                *(uint2*)(smem + OFF_K + nxt * 9216 + r * KSTRB + 2 * c) =
                    make_uint2(packhf(f.x, f.y), packhf(f.z, f.w));
            }
            __syncthreads();
            if (j < 6) {
                vf[0] = V4[(size_t)(j + 2) * 1024 + tid];
                vf[1] = V4[(size_t)(j + 2) * 1024 + tid + 512];
            }
        }
    }

    // ---- parallel reduction: 4 disjoint regions, one barrier ----
    __syncthreads();
    {
        static const int REDB[4] = {REDB0, REDB1, REDB2, REDB3};
        char* reg_ = smem + REDB[wn];
        #pragma unroll
        for (int nj = 0; nj < 8; ++nj) {
            int col = 8 * nj + 2 * lc;
            *(float2*)(reg_ + (r0 * RSTR + col) * 4) = make_float2(accO[nj][0], accO[nj][1]);
            *(float2*)(reg_ + (r1 * RSTR + col) * 4) = make_float2(accO[nj][2], accO[nj][3]);
        }
    }
    __syncthreads();

    #pragma unroll
    for (int t = 0; t < 2; ++t) {
        int idx = tid + 512 * t;
        int row = idx >> 4, c0 = (idx & 15) << 2;
        float4 a0 = *(float4*)(smem + REDB0 + (row * RSTR + c0) * 4);
        float4 a1 = *(float4*)(smem + REDB1 + (row * RSTR + c0) * 4);
        float4 a2 = *(float4*)(smem + REDB2 + (row * RSTR + c0) * 4);
        float4 a3 = *(float4*)(smem + REDB3 + (row * RSTR + c0) * 4);
        float4 o;
        o.x = (a0.x + a1.x) + (a2.x + a3.x);
        o.y = (a0.y + a1.y) + (a2.y + a3.y);
        o.z = (a0.z + a1.z) + (a2.z + a3.z);
        o.w = (a0.w + a1.w) + (a2.w + a3.w);
        *(float4*)(Op + row * DDIM + c0) = o;
    }
}

extern "C" void kernel_launch(void* const* d_in, const int* in_sizes, int n_in,
                              void* d_out, int out_size)
{
    const float* Q    = (const float*)d_in[0];
    const float* K    = (const float*)d_in[1];
    const float* V    = (const float*)d_in[2];
    const float* mask = (const float*)d_in[3];
    const float* adj  = (const float*)d_in[4];
    const float* dist = (const float*)d_in[5];

    float* outp  = (float*)d_out;
    float* pattn = outp + (size_t)BB * HH * SDIM * DDIM;

    precompute_C_kernel<<<BB * SDIM, 256>>>(adj, dist, mask);

    cudaFuncSetAttribute(attn_mma_kernel,
                         cudaFuncAttributeMaxDynamicSharedMemorySize, SMEM_BYTES);
    dim3 grid(SDIM / QT, HH, BB);
    attn_mma_kernel<<<grid, THREADS, SMEM_BYTES>>>(Q, K, V, mask, outp, pattn);
}

// round 15
// speedup vs baseline: 1.3438x; 1.0544x over previous
#include <cuda_runtime.h>
#include <cuda_fp16.h>
#include <math_constants.h>
#include <cstdint>

#define BB 16
#define HH 16
#define SDIM 512
#define DDIM 64
#define QT 64
#define THREADS 512
#define KSTRB 144

#define L_ATT 0.33f
#define L_DIST 0.33f
#define L_ADJ (1.0f - 0.33f - 0.33f)

// ---- smem map (bytes) ----
#define OFF_QS   0          // Q hi 64x144 fp16 (9216), lo at +9216
#define OFF_K    18432      // 2 bufs x 9216 (hi only); V chunks stream here in phase 3
#define RSTR     68
#define REDB0    0
#define REDB1    18432
#define REDB2    36864
#define REDB3    54272
#define OFF_RM   71680
#define OFF_RS   72704
#define OFF_MASK 73728
#define SMEM_BYTES 75776

#define GBAR(grp) asm volatile("bar.sync %0, %1;" :: "r"(1 + (grp)), "r"(128) : "memory")

__device__ float g_C[(size_t)BB * SDIM * SDIM];

__global__ __launch_bounds__(256) void precompute_C_kernel(
    const float* __restrict__ adj, const float* __restrict__ dist,
    const float* __restrict__ mask)
{
    int row = blockIdx.x;
    int b = row >> 9;
    const float* arow = adj  + (size_t)row * SDIM;
    const float* drow = dist + (size_t)row * SDIM;
    const float* mrow = mask + (size_t)b * SDIM;
    float* crow = g_C + (size_t)row * SDIM;
    int tid = threadIdx.x, w = tid >> 5, l = tid & 31;

    float a0 = arow[tid], a1 = arow[tid + 256];
    float d0 = drow[tid], d1 = drow[tid + 256];
    float m0 = mrow[tid], m1 = mrow[tid + 256];
    float x0 = (m0 == 0.0f) ? -CUDART_INF_F : -d0;
    float x1 = (m1 == 0.0f) ? -CUDART_INF_F : -d1;

    float asum = a0 + a1, xmax = fmaxf(x0, x1);
    #pragma unroll
    for (int o = 16; o > 0; o >>= 1) {
        asum += __shfl_xor_sync(0xffffffffu, asum, o);
        xmax = fmaxf(xmax, __shfl_xor_sync(0xffffffffu, xmax, o));
    }
    __shared__ float rs[8], rm[8], re[8];
    if (l == 0) { rs[w] = asum; rm[w] = xmax; }
    __syncthreads();
    float ts = 0.0f, tm = -CUDART_INF_F;
    #pragma unroll
    for (int i = 0; i < 8; i++) { ts += rs[i]; tm = fmaxf(tm, rm[i]); }

    float e0 = __expf(x0 - tm), e1 = __expf(x1 - tm), es = e0 + e1;
    #pragma unroll
    for (int o = 16; o > 0; o >>= 1) es += __shfl_xor_sync(0xffffffffu, es, o);
    if (l == 0) re[w] = es;
    __syncthreads();
    float te = 0.0f;
    #pragma unroll
    for (int i = 0; i < 8; i++) te += re[i];

    float inv_a = 1.0f / (ts + 1e-6f), inv_e = 1.0f / te;
    crow[tid]       = L_DIST * e0 * inv_e + L_ADJ * a0 * inv_a;
    crow[tid + 256] = L_DIST * e1 * inv_e + L_ADJ * a1 * inv_a;
}

__device__ __forceinline__ void mma_f16(float* c, const uint32_t* a, const uint32_t* b) {
    asm volatile("mma.sync.aligned.m16n8k16.row.col.f32.f16.f16.f32 "
        "{%0,%1,%2,%3}, {%4,%5,%6,%7}, {%8,%9}, {%0,%1,%2,%3};"
        : "+f"(c[0]), "+f"(c[1]), "+f"(c[2]), "+f"(c[3])
        : "r"(a[0]), "r"(a[1]), "r"(a[2]), "r"(a[3]), "r"(b[0]), "r"(b[1]));
}
__device__ __forceinline__ void ldm_x4(uint32_t* r, uint32_t a) {
    asm volatile("ldmatrix.sync.aligned.m8n8.x4.shared.b16 {%0,%1,%2,%3}, [%4];"
        : "=r"(r[0]), "=r"(r[1]), "=r"(r[2]), "=r"(r[3]) : "r"(a));
}
__device__ __forceinline__ void ldm_x4t(uint32_t* r, uint32_t a) {
    asm volatile("ldmatrix.sync.aligned.m8n8.x4.trans.shared.b16 {%0,%1,%2,%3}, [%4];"
        : "=r"(r[0]), "=r"(r[1]), "=r"(r[2]), "=r"(r[3]) : "r"(a));
}
__device__ __forceinline__ uint32_t smem_u32(const void* p) {
    uint32_t a;
    asm("{ .reg .u64 t; cvta.to.shared.u64 t, %1; cvt.u32.u64 %0, t; }" : "=r"(a) : "l"(p));
    return a;
}
__device__ __forceinline__ uint32_t packhf(float lo, float hi) {
    uint32_t r;
    asm("cvt.rn.f16x2.f32 %0, %1, %2;" : "=r"(r) : "f"(hi), "f"(lo));
    return r;
}
__device__ __forceinline__ float hround(float x) {
    return __half2float(__float2half_rn(x));
}

__global__ __launch_bounds__(512) void attn_mma_kernel(
    const float* __restrict__ Q, const float* __restrict__ K,
    const float* __restrict__ V, const float* __restrict__ mask,
    float* __restrict__ Og, float* __restrict__ Pg)
{
    extern __shared__ char smem[];
    uint32_t sb = smem_u32(smem);
    float* sMask = (float*)(smem + OFF_MASK);

    int tid = threadIdx.x;
    int wid = tid >> 5, l = tid & 31;
    int lr = l >> 2, lc = l & 3;
    int lr8 = l & 7, lg = (l >> 3) & 1, kg4 = l >> 4;
    int wm = wid >> 2, wn = wid & 3;   // m4 x n4
    int gtid = wm * 32 + l;            // 0..127 within n-group

    int qt = blockIdx.x, h = blockIdx.y, b = blockIdx.z;
    int q0 = qt * QT;
    size_t bh_ = (size_t)b * HH + h;
    const float* Qp = Q + (bh_ * SDIM + q0) * DDIM;
    const float* Kp = K + bh_ * SDIM * DDIM;
    const float* Vp = V + bh_ * SDIM * DDIM;
    const float* Mp = mask + (size_t)b * SDIM;
    const float* Cp = g_C + ((size_t)b * SDIM + q0) * SDIM;
    float* Op = Og + (bh_ * SDIM + q0) * DDIM;
    float* Pp = Pg + (bh_ * SDIM + q0) * SDIM;

    sMask[tid] = Mp[tid];

    // group-slice indices: group wn owns rows 16*wn..16*wn+15 of every 64-row tile
    int srow0 = (gtid >> 4);            // 0..7  (t=0)
    int srow1 = (gtid >> 4) + 8;        // 8..15 (t=1)
    int scol4 = gtid & 15;              // float4 column
    int grow0 = 16 * wn + srow0, grow1 = 16 * wn + srow1;

    // ---- Q (x 1/8) -> fp16 hi/lo smem (full CTA) ----
    {
        const float4* Q4 = (const float4*)Qp;
        #pragma unroll
        for (int t = 0; t < 2; ++t) {
            int idx = tid + 512 * t;
            float4 f = Q4[idx];
            int r = idx >> 4, c = (idx & 15) << 2;
            char* dst = smem + OFF_QS + r * KSTRB + 2 * c;
            float v0 = f.x * 0.125f, v1 = f.y * 0.125f, v2 = f.z * 0.125f, v3 = f.w * 0.125f;
            *(uint2*)dst = make_uint2(packhf(v0, v1), packhf(v2, v3));
            *(uint2*)(dst + 9216) = make_uint2(
                packhf(v0 - hround(v0), v1 - hround(v1)),
                packhf(v2 - hround(v2), v3 - hround(v3)));
        }
    }
    // ---- K tile 0 (group slice) -> buf0; prefetch tile 1 slice ----
    const float4* K4g = (const float4*)Kp;
    {
        float4 f0 = K4g[grow0 * 16 + scol4];
        float4 f1 = K4g[grow1 * 16 + scol4];
        *(uint2*)(smem + OFF_K + grow0 * KSTRB + 8 * scol4) =
            make_uint2(packhf(f0.x, f0.y), packhf(f0.z, f0.w));
        *(uint2*)(smem + OFF_K + grow1 * KSTRB + 8 * scol4) =
            make_uint2(packhf(f1.x, f1.y), packhf(f1.z, f1.w));
    }
    float4 pf[2];
    pf[0] = K4g[1024 + grow0 * 16 + scol4];
    pf[1] = K4g[1024 + grow1 * 16 + scol4];
    __syncthreads();

    // ---- resident Q fragments (hi + lo) ----
    uint32_t qah[4][4], qal[4][4];
    {
        uint32_t ra = sb + OFF_QS + (16 * wm + lr8 + 8 * lg) * KSTRB + 16 * kg4;
        #pragma unroll
        for (int ks = 0; ks < 4; ++ks) {
            ldm_x4(qah[ks], ra + ks * 32);
            ldm_x4(qal[ks], ra + 9216 + ks * 32);
        }
    }

    // ---- Phase 1: scores (regs), double-buffered K slices, group-local barriers ----
    float sc[8][2][4];
    #pragma unroll
    for (int kt = 0; kt < 8; ++kt) {
        #pragma unroll
        for (int nf = 0; nf < 2; ++nf)
            #pragma unroll
            for (int e = 0; e < 4; ++e) sc[kt][nf][e] = 0.0f;

        uint32_t rbase = sb + OFF_K + (kt & 1) * 9216
                         + (16 * wn + lr8 + 8 * kg4) * KSTRB + 16 * lg;
        uint32_t bh[2][4];
        ldm_x4(bh[0], rbase);
        #pragma unroll
        for (int ks = 0; ks < 4; ++ks) {
            int cc = ks & 1;
            if (ks < 3) ldm_x4(bh[cc ^ 1], rbase + 32 * (ks + 1));
            #pragma unroll
            for (int nf = 0; nf < 2; ++nf) {
                mma_f16(sc[kt][nf], qah[ks], bh[cc] + 2 * nf);
                mma_f16(sc[kt][nf], qal[ks], bh[cc] + 2 * nf);
            }
        }
        if (kt < 7) {
            char* kb = smem + OFF_K + ((kt + 1) & 1) * 9216;
            *(uint2*)(kb + grow0 * KSTRB + 8 * scol4) =
                make_uint2(packhf(pf[0].x, pf[0].y), packhf(pf[0].z, pf[0].w));
            *(uint2*)(kb + grow1 * KSTRB + 8 * scol4) =
                make_uint2(packhf(pf[1].x, pf[1].y), packhf(pf[1].z, pf[1].w));
            GBAR(wn);
            if (kt < 6) {
                pf[0] = K4g[(size_t)(kt + 2) * 1024 + grow0 * 16 + scol4];
                pf[1] = K4g[(size_t)(kt + 2) * 1024 + grow1 * 16 + scol4];
            }
        }
    }

    // ---- V chunk 0 LDG (group slice; latency hidden by softmax math) ----
    const float4* V4 = (const float4*)Vp;
    float4 vf[2];
    vf[0] = V4[grow0 * 16 + scol4];
    vf[1] = V4[grow1 * 16 + scol4];

    // ---- softmax: mask + row max ----
    int r0 = 16 * wm + lr, r1 = r0 + 8;
    {
        float2 mk;
        #pragma unroll
        for (int j = 0; j < 8; ++j)
            #pragma unroll
            for (int nf = 0; nf < 2; ++nf) {
                mk = *(float2*)(smem + OFF_MASK + 4 * (64 * j + 16 * wn + 8 * nf + 2 * lc));
                if (mk.x == 0.0f) { sc[j][nf][0] = -1e12f; sc[j][nf][2] = -1e12f; }
                if (mk.y == 0.0f) { sc[j][nf][1] = -1e12f; sc[j][nf][3] = -1e12f; }
            }
    }
    float mx0 = -CUDART_INF_F, mx1 = -CUDART_INF_F;
    #pragma unroll
    for (int j = 0; j < 8; ++j)
        #pragma unroll
        for (int nf = 0; nf < 2; ++nf) {
            mx0 = fmaxf(mx0, fmaxf(sc[j][nf][0], sc[j][nf][1]));
            mx1 = fmaxf(mx1, fmaxf(sc[j][nf][2], sc[j][nf][3]));
        }
    #pragma unroll
    for (int o = 1; o < 4; o <<= 1) {
        mx0 = fmaxf(mx0, __shfl_xor_sync(0xffffffffu, mx0, o));
        mx1 = fmaxf(mx1, __shfl_xor_sync(0xffffffffu, mx1, o));
    }
    if (lc == 0) {
        ((float*)(smem + OFF_RM))[r0 * 4 + wn] = mx0;
        ((float*)(smem + OFF_RM))[r1 * 4 + wn] = mx1;
    }
    // STS V chunk 0 slice -> buf0 (dead after kt7); RM full barrier covers it
    *(uint2*)(smem + OFF_K + grow0 * KSTRB + 8 * scol4) =
        make_uint2(packhf(vf[0].x, vf[0].y), packhf(vf[0].z, vf[0].w));
    *(uint2*)(smem + OFF_K + grow1 * KSTRB + 8 * scol4) =
        make_uint2(packhf(vf[1].x, vf[1].y), packhf(vf[1].z, vf[1].w));
    __syncthreads();
    {
        float4 m0 = *(float4*)(smem + OFF_RM + r0 * 16);
        float4 m1 = *(float4*)(smem + OFF_RM + r1 * 16);
        mx0 = fmaxf(fmaxf(m0.x, m0.y), fmaxf(m0.z, m0.w));
        mx1 = fmaxf(fmaxf(m1.x, m1.y), fmaxf(m1.z, m1.w));
    }
    // LDG V chunk 1 slice (hidden under exp/sum math)
    vf[0] = V4[1024 + grow0 * 16 + scol4];
    vf[1] = V4[1024 + grow1 * 16 + scol4];

    float s0 = 0.0f, s1 = 0.0f;
    #pragma unroll
    for (int j = 0; j < 8; ++j)
        #pragma unroll
        for (int nf = 0; nf < 2; ++nf) {
            sc[j][nf][0] = __expf(sc[j][nf][0] - mx0);
            sc[j][nf][1] = __expf(sc[j][nf][1] - mx0);
            sc[j][nf][2] = __expf(sc[j][nf][2] - mx1);
            sc[j][nf][3] = __expf(sc[j][nf][3] - mx1);
            s0 += sc[j][nf][0] + sc[j][nf][1];
            s1 += sc[j][nf][2] + sc[j][nf][3];
        }
    #pragma unroll
    for (int o = 1; o < 4; o <<= 1) {
        s0 += __shfl_xor_sync(0xffffffffu, s0, o);
        s1 += __shfl_xor_sync(0xffffffffu, s1, o);
    }
    if (lc == 0) {
        ((float*)(smem + OFF_RS))[r0 * 4 + wn] = s0;
        ((float*)(smem + OFF_RS))[r1 * 4 + wn] = s1;
    }
    // first C chunk prefetch while the sum barrier drains
    int colb = 16 * wn + 2 * lc;
    float2 cb[2][2][2];
    #pragma unroll
    for (int nf = 0; nf < 2; ++nf) {
        cb[0][0][nf] = __ldg((const float2*)(Cp + (size_t)r0 * SDIM + colb + 8 * nf));
        cb[0][1][nf] = __ldg((const float2*)(Cp + (size_t)r1 * SDIM + colb + 8 * nf));
    }
    __syncthreads();
    float inv0, inv1;
    {
        float4 t0 = *(float4*)(smem + OFF_RS + r0 * 16);
        float4 t1 = *(float4*)(smem + OFF_RS + r1 * 16);
        inv0 = 1.0f / (t0.x + t0.y + t0.z + t0.w);
        inv1 = 1.0f / (t1.x + t1.y + t1.z + t1.w);
    }

    // ---- fused phase 2+3 per 64-key chunk j; V slices streamed, group barriers ----
    float accO[8][4];
    #pragma unroll
    for (int nj = 0; nj < 8; ++nj)
        #pragma unroll
        for (int e = 0; e < 4; ++e) accO[nj][e] = 0.0f;

    #pragma unroll
    for (int j = 0; j < 8; ++j) {
        int cur = j & 1, nxt = cur ^ 1;
        if (j < 7) {
            int coln = 64 * (j + 1) + colb;
            #pragma unroll
            for (int nf = 0; nf < 2; ++nf) {
                cb[nxt][0][nf] = __ldg((const float2*)(Cp + (size_t)r0 * SDIM + coln + 8 * nf));
                cb[nxt][1][nf] = __ldg((const float2*)(Cp + (size_t)r1 * SDIM + coln + 8 * nf));
            }
        }
        uint32_t wah[4], wal[4];
        #pragma unroll
        for (int nf = 0; nf < 2; ++nf) {
            int col = 64 * j + colb + 8 * nf;
            float p00 = sc[j][nf][0] * inv0, p01 = sc[j][nf][1] * inv0;
            float p10 = sc[j][nf][2] * inv1, p11 = sc[j][nf][3] * inv1;
            __stcs((float2*)(Pp + (size_t)r0 * SDIM + col), make_float2(p00, p01));
            __stcs((float2*)(Pp + (size_t)r1 * SDIM + col), make_float2(p10, p11));
            float w00 = fmaf(L_ATT, p00, cb[cur][0][nf].x);
            float w01 = fmaf(L_ATT, p01, cb[cur][0][nf].y);
            float w10 = fmaf(L_ATT, p10, cb[cur][1][nf].x);
            float w11 = fmaf(L_ATT, p11, cb[cur][1][nf].y);
            wah[2 * nf]     = packhf(w00, w01);
            wah[2 * nf + 1] = packhf(w10, w11);
            wal[2 * nf]     = packhf(w00 - hround(w00), w01 - hround(w01));
            wal[2 * nf + 1] = packhf(w10 - hround(w10), w11 - hround(w11));
        }

        uint32_t vbase = sb + OFF_K + cur * 9216
                         + (16 * wn + lr8 + 8 * lg) * KSTRB + 16 * kg4;
        uint32_t vb[2][4];
        ldm_x4t(vb[0], vbase);
        #pragma unroll
        for (int njp = 0; njp < 4; ++njp) {
            int vc = njp & 1;
            if (njp < 3) ldm_x4t(vb[vc ^ 1], vbase + 32 * (njp + 1));
            mma_f16(accO[2 * njp],     wah, vb[vc]);
            mma_f16(accO[2 * njp],     wal, vb[vc]);
            mma_f16(accO[2 * njp + 1], wah, vb[vc] + 2);
            mma_f16(accO[2 * njp + 1], wal, vb[vc] + 2);
        }

        if (j < 7) {
            char* kb = smem + OFF_K + nxt * 9216;
            *(uint2*)(kb + grow0 * KSTRB + 8 * scol4) =
                make_uint2(packhf(vf[0].x, vf[0].y), packhf(vf[0].z, vf[0].w));
            *(uint2*)(kb + grow1 * KSTRB + 8 * scol4) =
                make_uint2(packhf(vf[1].x, vf[1].y), packhf(vf[1].z, vf[1].w));
            GBAR(wn);
            if (j < 6) {
                vf[0] = V4[(size_t)(j + 2) * 1024 + grow0 * 16 + scol4];
                vf[1] = V4[(size_t)(j + 2) * 1024 + grow1 * 16 + scol4];
            }
        }
    }

    // ---- parallel reduction: 4 disjoint regions, one barrier ----
    __syncthreads();    // also protects reduction regions overlaying Q/K bufs
    {
        static const int REDB[4] = {REDB0, REDB1, REDB2, REDB3};
        char* reg_ = smem + REDB[wn];
        #pragma unroll
        for (int nj = 0; nj < 8; ++nj) {
            int col = 8 * nj + 2 * lc;
            *(float2*)(reg_ + (r0 * RSTR + col) * 4) = make_float2(accO[nj][0], accO[nj][1]);
            *(float2*)(reg_ + (r1 * RSTR + col) * 4) = make_float2(accO[nj][2], accO[nj][3]);
        }
    }
    __syncthreads();

    #pragma unroll
    for (int t = 0; t < 2; ++t) {
        int idx = tid + 512 * t;
        int row = idx >> 4, c0 = (idx & 15) << 2;
        float4 a0 = *(float4*)(smem + REDB0 + (row * RSTR + c0) * 4);
        float4 a1 = *(float4*)(smem + REDB1 + (row * RSTR + c0) * 4);
        float4 a2 = *(float4*)(smem + REDB2 + (row * RSTR + c0) * 4);
        float4 a3 = *(float4*)(smem + REDB3 + (row * RSTR + c0) * 4);
        float4 o;
        o.x = (a0.x + a1.x) + (a2.x + a3.x);
        o.y = (a0.y + a1.y) + (a2.y + a3.y);
        o.z = (a0.z + a1.z) + (a2.z + a3.z);
        o.w = (a0.w + a1.w) + (a2.w + a3.w);
        *(float4*)(Op + row * DDIM + c0) = o;
    }
}

extern "C" void kernel_launch(void* const* d_in, const int* in_sizes, int n_in,
                              void* d_out, int out_size)
{
    const float* Q    = (const float*)d_in[0];
    const float* K    = (const float*)d_in[1];
    const float* V    = (const float*)d_in[2];
    const float* mask = (const float*)d_in[3];
    const float* adj  = (const float*)d_in[4];
    const float* dist = (const float*)d_in[5];

    float* outp  = (float*)d_out;
    float* pattn = outp + (size_t)BB * HH * SDIM * DDIM;

    precompute_C_kernel<<<BB * SDIM, 256>>>(adj, dist, mask);

    cudaFuncSetAttribute(attn_mma_kernel,
                         cudaFuncAttributeMaxDynamicSharedMemorySize, SMEM_BYTES);
    dim3 grid(SDIM / QT, HH, BB);
    attn_mma_kernel<<<grid, THREADS, SMEM_BYTES>>>(Q, K, V, mask, outp, pattn);
}